// round 8
// baseline (speedup 1.0000x reference)
#include <cuda_runtime.h>
#include <math.h>

// ---------------- problem constants (fixed by the reference) ----------------
#define BB 2
#define LL 2048
#define HH 768
#define EE 1536
#define NNS 16           // state dim N
#define RRK 4            // dt rank R
#define CC 3
#define NLAYER 8
#define TT (BB*LL)       // 4096 rows
#define NCH 16           // scan chunks per sequence
#define TCH (LL/NCH)     // 128 steps per chunk

typedef unsigned long long u64;

// ---------------- scratch (device globals: no runtime allocation) ----------
__device__ float g_hs  [TT*HH];
__device__ float g_x   [TT*HH];
__device__ float g_proj[TT*2*EE];
__device__ float g_u   [TT*EE];
__device__ float g_dbc [TT*36];
__device__ float g_dt  [TT*EE];
__device__ float g_y   [TT*EE];
__device__ float g_cP   [BB*NCH*NNS*EE];
__device__ float g_cH   [BB*NCH*NNS*EE];
__device__ float g_hinit[BB*NCH*NNS*EE];
__device__ float g_t1  [TT*HH];
__device__ float g_t2  [TT*HH];
__device__ float g_accb[TT*HH];

// ---------------- helpers ----------------
__device__ __forceinline__ float silu_f(float v)    { return v / (1.0f + expf(-v)); }
__device__ __forceinline__ float sigmoid_f(float v) { return 1.0f / (1.0f + expf(-v)); }
__device__ __forceinline__ float softplus_f(float v){ return (v > 20.0f) ? v : log1pf(expf(v)); }

// packed f32x2 ops (Blackwell): one instruction = 2 fp32 FMAs per lane.
__device__ __forceinline__ u64 pk2(float x, float y)
{ u64 r; asm("mov.b64 %0, {%1, %2};" : "=l"(r) : "f"(x), "f"(y)); return r; }
__device__ __forceinline__ void upk2(u64 v, float& x, float& y)
{ asm("mov.b64 {%0, %1}, %2;" : "=f"(x), "=f"(y) : "l"(v)); }
__device__ __forceinline__ u64 ffma2(u64 a, u64 b, u64 c)
{ u64 d; asm("fma.rn.f32x2 %0, %1, %2, %3;" : "=l"(d) : "l"(a), "l"(b), "l"(c)); return d; }

// ---------------- embedding ----------------
__global__ void embed_kernel(const int* __restrict__ ids,
                             const float* __restrict__ tok,
                             const float* __restrict__ pos,
                             float* __restrict__ hs)
{
    int g = blockIdx.x * blockDim.x + threadIdx.x;   // TT*HH
    if (g >= TT*HH) return;
    int h   = g % HH;
    int row = g / HH;
    int t   = row % LL;
    hs[g] = tok[(size_t)ids[row]*HH + h] + pos[(size_t)t*HH + h];
}

// ---------------- layernorm (one block per row of 768) ----------------
__global__ __launch_bounds__(256) void ln_kernel(const float* __restrict__ in,
                                                 const float* __restrict__ w,
                                                 const float* __restrict__ b,
                                                 float* __restrict__ out)
{
    __shared__ float red[256];
    int row = blockIdx.x, tid = threadIdx.x;
    const float* x = in + (size_t)row*HH;
    float v0 = x[tid], v1 = x[tid+256], v2 = x[tid+512];
    red[tid] = v0 + v1 + v2;
    __syncthreads();
    #pragma unroll
    for (int s = 128; s > 0; s >>= 1) { if (tid < s) red[tid] += red[tid+s]; __syncthreads(); }
    float mean = red[0] * (1.0f/768.0f);
    __syncthreads();
    float d0 = v0-mean, d1 = v1-mean, d2 = v2-mean;
    red[tid] = d0*d0 + d1*d1 + d2*d2;
    __syncthreads();
    #pragma unroll
    for (int s = 128; s > 0; s >>= 1) { if (tid < s) red[tid] += red[tid+s]; __syncthreads(); }
    float inv = rsqrtf(red[0] * (1.0f/768.0f) + 1e-5f);
    float* o = out + (size_t)row*HH;
    o[tid]     = d0*inv*w[tid]     + b[tid];
    o[tid+256] = d1*inv*w[tid+256] + b[tid+256];
    o[tid+512] = d2*inv*w[tid+512] + b[tid+512];
}

// ---------------- fp32 GEMM with packed-f32x2 inner loop -------------------
// C = act(A*W + bias) [+res] [accum].  A: MxK row-major, W: KxN row-major.
// M%128==0, K%16==0, N%64==0.  128x64 block tile, 8x4 per thread,
// accumulators held as 16x f32x2 pairs (pairs along N).
__global__ __launch_bounds__(256) void gemm_kernel(
    const float* __restrict__ A, const float* __restrict__ W,
    const float* __restrict__ bias, const float* __restrict__ Rres,
    float* __restrict__ Cout, int M, int Kd, int Nd, int act, int accum)
{
    __shared__ __align__(16) float As[16][132];
    __shared__ __align__(16) float Bs[16][64];
    const int tid = threadIdx.x;
    const int bm  = blockIdx.y * 128;
    const int bn  = blockIdx.x * 64;
    const int m0  = (tid >> 4) * 8;
    const int n0  = (tid & 15) * 4;
    const int arow = tid >> 2;
    const int acol = (tid & 3) * 4;
    const int brow = tid >> 4;
    const int bcol = (tid & 15) * 4;

    u64 acc2[8][2];
    #pragma unroll
    for (int i = 0; i < 8; i++) { acc2[i][0] = 0ull; acc2[i][1] = 0ull; }

    for (int k0 = 0; k0 < Kd; k0 += 16) {
        #pragma unroll
        for (int r = 0; r < 2; r++) {
            int m = arow + r*64;
            const float4 v = *(const float4*)(A + (size_t)(bm + m)*Kd + k0 + acol);
            As[acol+0][m] = v.x; As[acol+1][m] = v.y;
            As[acol+2][m] = v.z; As[acol+3][m] = v.w;
        }
        {
            const float4 v = *(const float4*)(W + (size_t)(k0 + brow)*Nd + bn + bcol);
            *(float4*)(&Bs[brow][bcol]) = v;
        }
        __syncthreads();
        #pragma unroll
        for (int kk = 0; kk < 16; kk++) {
            float4 a0 = *(const float4*)(&As[kk][m0]);
            float4 a1 = *(const float4*)(&As[kk][m0+4]);
            float4 b0 = *(const float4*)(&Bs[kk][n0]);
            u64 bp0 = pk2(b0.x, b0.y);
            u64 bp1 = pk2(b0.z, b0.w);
            float af[8] = {a0.x,a0.y,a0.z,a0.w,a1.x,a1.y,a1.z,a1.w};
            #pragma unroll
            for (int i = 0; i < 8; i++) {
                u64 ap = pk2(af[i], af[i]);
                acc2[i][0] = ffma2(ap, bp0, acc2[i][0]);
                acc2[i][1] = ffma2(ap, bp1, acc2[i][1]);
            }
        }
        __syncthreads();
    }

    #pragma unroll
    for (int i = 0; i < 8; i++) {
        float acc[4];
        upk2(acc2[i][0], acc[0], acc[1]);
        upk2(acc2[i][1], acc[2], acc[3]);
        int m = bm + m0 + i;
        #pragma unroll
        for (int j = 0; j < 4; j++) {
            int n = bn + n0 + j;
            float v = acc[j] + bias[n];
            if (act) v = silu_f(v);
            size_t idx = (size_t)m * Nd + n;
            if (Rres)  v += Rres[idx];
            if (accum) Cout[idx] += v;
            else       Cout[idx]  = v;
        }
    }
}

// ---------------- causal depthwise conv (K=4) + SiLU, reads xm from proj ----
__global__ void conv_silu_kernel(const float* __restrict__ proj,
                                 const float* __restrict__ cw,
                                 const float* __restrict__ cb,
                                 float* __restrict__ u)
{
    int g = blockIdx.x * blockDim.x + threadIdx.x;   // TT*EE
    if (g >= TT*EE) return;
    int e   = g % EE;
    int row = g / EE;
    int t   = row % LL;
    int b   = row / LL;
    float acc = cb[e];
    #pragma unroll
    for (int j = 0; j < 4; j++) {
        int tt = t - 3 + j;
        if (tt >= 0)
            acc = fmaf(proj[(size_t)(b*LL + tt)*(2*EE) + e], cw[e*4 + j], acc);
    }
    u[g] = silu_f(acc);
}

// ---------------- dbc = u @ xproj_w  (4096 x 1536 x 36 skinny GEMM) --------
__global__ __launch_bounds__(288) void dbc_kernel(const float* __restrict__ u,
                                                  const float* __restrict__ w,
                                                  float* __restrict__ dbc)
{
    __shared__ float su[EE];
    __shared__ float part[8][36];
    int row = blockIdx.x;
    for (int i = threadIdx.x; i < EE; i += 288) su[i] = u[(size_t)row*EE + i];
    __syncthreads();
    int j = threadIdx.x % 36, s = threadIdx.x / 36;   // 36 cols x 8 k-slices
    float acc = 0.0f;
    int k0 = s * (EE/8);
    for (int k = k0; k < k0 + EE/8; k++)
        acc = fmaf(su[k], w[k*36 + j], acc);
    part[s][j] = acc;
    __syncthreads();
    if (threadIdx.x < 36) {
        float t = 0.0f;
        #pragma unroll
        for (int ss = 0; ss < 8; ss++) t += part[ss][threadIdx.x];
        dbc[row*36 + threadIdx.x] = t;
    }
}

// ---------------- dt = softplus(dbc[:, :4] @ dt_w + dt_b) ------------------
__global__ void dt_kernel(const float* __restrict__ dbc,
                          const float* __restrict__ dtw,
                          const float* __restrict__ dtb,
                          float* __restrict__ dt)
{
    int g = blockIdx.x * blockDim.x + threadIdx.x;   // TT*EE
    if (g >= TT*EE) return;
    int e = g % EE, row = g / EE;
    float v = dtb[e];
    #pragma unroll
    for (int r = 0; r < 4; r++)
        v = fmaf(dbc[row*36 + r], dtw[r*EE + e], v);
    dt[g] = softplus_f(v);
}

// ---------------- scan pass A: per-chunk (prod dA, h'|h0=0) ----------------
__global__ void scan_chunk_kernel(const float* __restrict__ dtp,
                                  const float* __restrict__ up,
                                  const float* __restrict__ dbc,
                                  const float* __restrict__ A_log,
                                  float* __restrict__ cP, float* __restrict__ cH)
{
    int g = blockIdx.x * blockDim.x + threadIdx.x;
    int e = g % EE;
    int n = (g / EE) % NNS;
    int c = (g / (EE*NNS)) % NCH;
    int b =  g / (EE*NNS*NCH);
    float Aen = -expf(A_log[e*NNS + n]);
    float p = 1.0f, h = 0.0f;
    int rbase = b*LL + c*TCH;
    for (int t = 0; t < TCH; t++) {
        int row   = rbase + t;
        float dtv = dtp[(size_t)row*EE + e];
        float uv  = up [(size_t)row*EE + e];
        float bv  = dbc[row*36 + 4 + n];
        float dA  = expf(dtv * Aen);
        p *= dA;
        h = fmaf(h, dA, dtv * uv * bv);
    }
    size_t idx = ((size_t)((b*NCH + c)*NNS + n))*EE + e;
    cP[idx] = p; cH[idx] = h;
}

// ---------------- scan pass B: sequential carry across 16 chunks -----------
__global__ void scan_carry_kernel(const float* __restrict__ cP,
                                  const float* __restrict__ cH,
                                  float* __restrict__ hinit)
{
    int g = blockIdx.x * blockDim.x + threadIdx.x;   // BB*NNS*EE
    if (g >= BB*NNS*EE) return;
    int e = g % EE;
    int n = (g / EE) % NNS;
    int b =  g / (EE*NNS);
    float h = 0.0f;
    for (int c = 0; c < NCH; c++) {
        size_t idx = ((size_t)((b*NCH + c)*NNS + n))*EE + e;
        hinit[idx] = h;
        h = fmaf(cP[idx], h, cH[idx]);
    }
}

// ---------------- scan pass C: rescan with carry, reduce over n, gate ------
__global__ void scan_y_kernel(const float* __restrict__ dtp,
                              const float* __restrict__ up,
                              const float* __restrict__ dbc,
                              const float* __restrict__ hinit,
                              const float* __restrict__ A_log,
                              const float* __restrict__ Dv,
                              const float* __restrict__ proj,
                              float* __restrict__ y)
{
    int g = blockIdx.x * blockDim.x + threadIdx.x;
    int n = g % NNS;
    int e = (g / NNS) % EE;
    int c = (g / (NNS*EE)) % NCH;
    int b =  g / (NNS*EE*NCH);
    float Aen  = -expf(A_log[e*NNS + n]);
    float h    = hinit[((size_t)((b*NCH + c)*NNS + n))*EE + e];
    float Dval = Dv[e];
    int t0 = c*TCH;
    for (int t = t0; t < t0 + TCH; t++) {
        int row   = b*LL + t;
        float dtv = dtp[(size_t)row*EE + e];
        float uv  = up [(size_t)row*EE + e];
        float bv  = dbc[row*36 + 4  + n];
        float cv  = dbc[row*36 + 20 + n];
        h = fmaf(h, expf(dtv * Aen), dtv * uv * bv);
        float part = h * cv;
        part += __shfl_xor_sync(0xffffffffu, part, 8);
        part += __shfl_xor_sync(0xffffffffu, part, 4);
        part += __shfl_xor_sync(0xffffffffu, part, 2);
        part += __shfl_xor_sync(0xffffffffu, part, 1);
        if (n == 0) {
            float gate = proj[(size_t)row*(2*EE) + EE + e];
            y[(size_t)row*EE + e] = (part + uv*Dval) * sigmoid_f(gate);
        }
    }
}

// ---------------- small elementwise ----------------
__global__ void frac_add_kernel(float* __restrict__ hs, const float* __restrict__ acc, int n)
{
    int g = blockIdx.x * blockDim.x + threadIdx.x;
    if (g < n) hs[g] = fmaf(acc[g], 0.5f/3.0f, hs[g]);
}

// ---------------- host orchestration ----------------
extern "C" void kernel_launch(void* const* d_in, const int* in_sizes, int n_in,
                              void* d_out, int out_size)
{
    const int*   input_ids = (const int*)  d_in[0];
    const float* tok_emb   = (const float*)d_in[1];
    const float* pos_emb   = (const float*)d_in[2];
    const float* ln_w      = (const float*)d_in[3];
    const float* ln_b      = (const float*)d_in[4];
    const float* in_w      = (const float*)d_in[5];
    const float* in_b      = (const float*)d_in[6];
    const float* conv_w    = (const float*)d_in[7];
    const float* conv_b    = (const float*)d_in[8];
    const float* xproj_w   = (const float*)d_in[9];
    const float* dt_w      = (const float*)d_in[10];
    const float* dt_b      = (const float*)d_in[11];
    const float* A_log     = (const float*)d_in[12];
    const float* Dvec      = (const float*)d_in[13];
    const float* out_w     = (const float*)d_in[14];
    const float* out_b     = (const float*)d_in[15];
    const float* frac_w    = (const float*)d_in[16];
    const float* frac_b    = (const float*)d_in[17];
    const float* fln_w     = (const float*)d_in[18];
    const float* fln_b     = (const float*)d_in[19];
    float* outp = (float*)d_out;

    float *hs, *x, *proj, *u, *dbc, *dt, *y, *cP, *cH, *hinit, *t1, *t2, *accb;
    cudaGetSymbolAddress((void**)&hs,    g_hs);
    cudaGetSymbolAddress((void**)&x,     g_x);
    cudaGetSymbolAddress((void**)&proj,  g_proj);
    cudaGetSymbolAddress((void**)&u,     g_u);
    cudaGetSymbolAddress((void**)&dbc,   g_dbc);
    cudaGetSymbolAddress((void**)&dt,    g_dt);
    cudaGetSymbolAddress((void**)&y,     g_y);
    cudaGetSymbolAddress((void**)&cP,    g_cP);
    cudaGetSymbolAddress((void**)&cH,    g_cH);
    cudaGetSymbolAddress((void**)&hinit, g_hinit);
    cudaGetSymbolAddress((void**)&t1,    g_t1);
    cudaGetSymbolAddress((void**)&t2,    g_t2);
    cudaGetSymbolAddress((void**)&accb,  g_accb);

    const int EW = TT*HH;          // elementwise over hidden
    const int EWE = TT*EE;
    const int SCAN_T = BB*NCH*NNS*EE;    // 786432

    embed_kernel<<<(EW + 255)/256, 256>>>(input_ids, tok_emb, pos_emb, hs);

    for (int l = 0; l < NLAYER; l++) {
        // x = LN(hs)
        ln_kernel<<<TT, 256>>>(hs, ln_w + l*HH, ln_b + l*HH, x);
        // proj = x @ in_w + in_b      (4096 x 768 x 3072)
        gemm_kernel<<<dim3(2*EE/64, TT/128), 256>>>(
            x, in_w + (size_t)l*HH*2*EE, in_b + l*2*EE, nullptr, proj,
            TT, HH, 2*EE, 0, 0);
        // u = silu(causal_dwconv(proj[:, :E]))
        conv_silu_kernel<<<(EWE + 255)/256, 256>>>(proj, conv_w + l*EE*4, conv_b + l*EE, u);
        // dbc = u @ xproj_w
        dbc_kernel<<<TT, 288>>>(u, xproj_w + (size_t)l*EE*36, dbc);
        // dt = softplus(dbc[:, :4] @ dt_w + dt_b)
        dt_kernel<<<(EWE + 255)/256, 256>>>(dbc, dt_w + l*RRK*EE, dt_b + l*EE, dt);
        // chunked selective scan
        scan_chunk_kernel<<<SCAN_T/256, 256>>>(dt, u, dbc, A_log + (size_t)l*EE*NNS, cP, cH);
        scan_carry_kernel<<<(BB*NNS*EE + 255)/256, 256>>>(cP, cH, hinit);
        scan_y_kernel<<<SCAN_T/256, 256>>>(dt, u, dbc, hinit,
            A_log + (size_t)l*EE*NNS, Dvec + l*EE, proj, y);
        // hs = y @ out_w + out_b + hs  (residual fused)
        gemm_kernel<<<dim3(HH/64, TT/128), 256>>>(
            y, out_w + (size_t)l*EE*HH, out_b + l*HH, hs, hs,
            TT, EE, HH, 0, 0);
        // fractal refinement: acc = sum_i silu^3(hs; W_i); hs += acc/6
        for (int i = 0; i < CC; i++) {
            const float* Wp = frac_w + (size_t)(l*CC + i)*HH*HH;
            const float* bp = frac_b + (size_t)(l*CC + i)*HH;
            gemm_kernel<<<dim3(HH/64, TT/128), 256>>>(hs, Wp, bp, nullptr, t1, TT, HH, HH, 1, 0);
            gemm_kernel<<<dim3(HH/64, TT/128), 256>>>(t1, Wp, bp, nullptr, t2, TT, HH, HH, 1, 0);
            // i==0 writes accb (no zero pass needed); i>0 accumulates
            gemm_kernel<<<dim3(HH/64, TT/128), 256>>>(t2, Wp, bp, nullptr, accb, TT, HH, HH, 1, (i > 0) ? 1 : 0);
        }
        frac_add_kernel<<<(EW + 255)/256, 256>>>(hs, accb, EW);
    }

    // final layernorm -> output (float32)
    ln_kernel<<<TT, 256>>>(hs, fln_w, fln_b, outp);
    (void)in_sizes; (void)n_in; (void)out_size;
}

// round 10
// speedup vs baseline: 1.6047x; 1.6047x over previous
#include <cuda_runtime.h>
#include <cuda_bf16.h>
#include <math.h>
#include <stdint.h>

// ---------------- problem constants (fixed by the reference) ----------------
#define BB 2
#define LL 2048
#define HH 768
#define EE 1536
#define NNS 16           // state dim N
#define RRK 4            // dt rank R
#define CC 3
#define NLAYER 8
#define TT (BB*LL)       // 4096 rows
#define NCH 16           // scan chunks per sequence
#define TCH (LL/NCH)     // 128 steps per chunk

// ---------------- scratch (device globals: no runtime allocation) ----------
__device__ float g_hs  [TT*HH];
__device__ float g_x   [TT*HH];
__device__ float g_proj[TT*2*EE];
__device__ float g_u   [TT*EE];
__device__ float g_dbc [TT*36];
__device__ float g_dt  [TT*EE];
__device__ float g_y   [TT*EE];
__device__ float g_cP   [BB*NCH*NNS*EE];
__device__ float g_cH   [BB*NCH*NNS*EE];
__device__ float g_hinit[BB*NCH*NNS*EE];
__device__ float g_t1  [TT*HH];
__device__ float g_t2  [TT*HH];
__device__ float g_accb[TT*HH];

// bf16 hi/lo split buffers for tensor-core GEMM operands
__device__ __nv_bfloat16 g_Ah [TT*EE];   // activations (max K = 1536)
__device__ __nv_bfloat16 g_Al [TT*EE];
__device__ __nv_bfloat16 g_Ah2[TT*HH];   // hs (reused across fractal branches)
__device__ __nv_bfloat16 g_Al2[TT*HH];
__device__ __nv_bfloat16 g_Wth[2*EE*HH]; // transposed weight [N,K], max 3072*768
__device__ __nv_bfloat16 g_Wtl[2*EE*HH];

// ---------------- helpers ----------------
__device__ __forceinline__ float silu_f(float v)    { return v / (1.0f + expf(-v)); }
__device__ __forceinline__ float sigmoid_f(float v) { return 1.0f / (1.0f + expf(-v)); }
__device__ __forceinline__ float softplus_f(float v){ return (v > 20.0f) ? v : log1pf(expf(v)); }

// mma.sync m16n8k16 bf16 -> fp32 accum (portable PTX, works at compute_103)
__device__ __forceinline__ void mma16816(float* d, const uint32_t* a, const uint32_t* b)
{
    asm volatile(
        "mma.sync.aligned.m16n8k16.row.col.f32.bf16.bf16.f32 "
        "{%0,%1,%2,%3}, {%4,%5,%6,%7}, {%8,%9}, {%0,%1,%2,%3};"
        : "+f"(d[0]), "+f"(d[1]), "+f"(d[2]), "+f"(d[3])
        : "r"(a[0]), "r"(a[1]), "r"(a[2]), "r"(a[3]), "r"(b[0]), "r"(b[1]));
}

// ---------------- embedding ----------------
__global__ void embed_kernel(const int* __restrict__ ids,
                             const float* __restrict__ tok,
                             const float* __restrict__ pos,
                             float* __restrict__ hs)
{
    int g = blockIdx.x * blockDim.x + threadIdx.x;   // TT*HH
    if (g >= TT*HH) return;
    int h   = g % HH;
    int row = g / HH;
    int t   = row % LL;
    hs[g] = tok[(size_t)ids[row]*HH + h] + pos[(size_t)t*HH + h];
}

// ---------------- layernorm (one block per row of 768) ----------------
__global__ __launch_bounds__(256) void ln_kernel(const float* __restrict__ in,
                                                 const float* __restrict__ w,
                                                 const float* __restrict__ b,
                                                 float* __restrict__ out)
{
    __shared__ float red[256];
    int row = blockIdx.x, tid = threadIdx.x;
    const float* x = in + (size_t)row*HH;
    float v0 = x[tid], v1 = x[tid+256], v2 = x[tid+512];
    red[tid] = v0 + v1 + v2;
    __syncthreads();
    #pragma unroll
    for (int s = 128; s > 0; s >>= 1) { if (tid < s) red[tid] += red[tid+s]; __syncthreads(); }
    float mean = red[0] * (1.0f/768.0f);
    __syncthreads();
    float d0 = v0-mean, d1 = v1-mean, d2 = v2-mean;
    red[tid] = d0*d0 + d1*d1 + d2*d2;
    __syncthreads();
    #pragma unroll
    for (int s = 128; s > 0; s >>= 1) { if (tid < s) red[tid] += red[tid+s]; __syncthreads(); }
    float inv = rsqrtf(red[0] * (1.0f/768.0f) + 1e-5f);
    float* o = out + (size_t)row*HH;
    o[tid]     = d0*inv*w[tid]     + b[tid];
    o[tid+256] = d1*inv*w[tid+256] + b[tid+256];
    o[tid+512] = d2*inv*w[tid+512] + b[tid+512];
}

// ---------------- fp32 -> bf16 hi/lo split (elementwise) -------------------
__global__ void convA_kernel(const float* __restrict__ X,
                             __nv_bfloat16* __restrict__ Xh,
                             __nv_bfloat16* __restrict__ Xl, int n)
{
    int g = blockIdx.x * blockDim.x + threadIdx.x;
    if (g >= n) return;
    float v = X[g];
    __nv_bfloat16 h = __float2bfloat16(v);
    Xh[g] = h;
    Xl[g] = __float2bfloat16(v - __bfloat162float(h));
}

// ---------------- weight transpose + split: W[K,N] -> Wt[N,K] hi/lo --------
__global__ __launch_bounds__(256) void convW_kernel(const float* __restrict__ W,
                                                    __nv_bfloat16* __restrict__ Wth,
                                                    __nv_bfloat16* __restrict__ Wtl,
                                                    int Kd, int Nd)
{
    __shared__ float tile[32][33];
    int kb = blockIdx.y*32, nb = blockIdx.x*32;
    int tx = threadIdx.x & 31, ty = threadIdx.x >> 5;   // 32x8
    #pragma unroll
    for (int r = 0; r < 32; r += 8)
        tile[ty+r][tx] = W[(size_t)(kb+ty+r)*Nd + nb+tx];
    __syncthreads();
    #pragma unroll
    for (int r = 0; r < 32; r += 8) {
        int n = nb + ty + r, k = kb + tx;
        float v = tile[tx][ty+r];
        __nv_bfloat16 h = __float2bfloat16(v);
        Wth[(size_t)n*Kd + k] = h;
        Wtl[(size_t)n*Kd + k] = __float2bfloat16(v - __bfloat162float(h));
    }
}

// ---------------- tensor-core split-bf16 GEMM via mma.sync -----------------
// C[M,N] = act(A*W + bias) [+res] [accum]
// A pre-split (Ah,Al) [M,K] bf16 row-major; W pre-split+transposed (Bh,Bl)
// [N,K] bf16 row-major. D = Ah*Bh^T + Ah*Bl^T + Al*Bh^T, fp32 accumulate.
// Block 128x128, 8 warps (4x2), warp tile 32x64. K-chunk 64.
// M%128==0, N%128==0, K%64==0.
#define KC   64
#define AST  72     // smem row stride (bf16 elems): conflict-free frag loads
#define MM_SMEM (4*128*AST*2)

__global__ __launch_bounds__(256) void mma_gemm(
    const __nv_bfloat16* __restrict__ Ah, const __nv_bfloat16* __restrict__ Al,
    const __nv_bfloat16* __restrict__ Bh, const __nv_bfloat16* __restrict__ Bl,
    const float* __restrict__ bias, const float* __restrict__ Rres,
    float* __restrict__ Cout, int M, int Kd, int Nd, int act, int accum)
{
    extern __shared__ __align__(16) __nv_bfloat16 sm[];
    __nv_bfloat16* Ash = sm;
    __nv_bfloat16* Asl = Ash + 128*AST;
    __nv_bfloat16* Bsh = Asl + 128*AST;
    __nv_bfloat16* Bsl = Bsh + 128*AST;

    const int tid  = threadIdx.x;
    const int wid  = tid >> 5, lane = tid & 31;
    const int bm   = blockIdx.y * 128, bn = blockIdx.x * 128;
    const int wm   = (wid & 3) * 32;      // warp row offset
    const int wn   = (wid >> 2) * 64;     // warp col offset
    const int r    = lane >> 2, c = lane & 3;

    float acc[2][8][4];
    #pragma unroll
    for (int mt = 0; mt < 2; mt++)
        #pragma unroll
        for (int nt = 0; nt < 8; nt++)
            #pragma unroll
            for (int j = 0; j < 4; j++) acc[mt][nt][j] = 0.0f;

    const int nkc = Kd / KC;
    for (int kc = 0; kc < nkc; kc++) {
        const size_t koff = (size_t)kc * KC;
        // fill 4 tiles 128xKC bf16 (uint4 = 8 bf16)
        #pragma unroll
        for (int i = 0; i < 4; i++) {
            int t    = tid + i*256;           // 0..1023
            int row  = t >> 3;
            int col8 = (t & 7) * 8;
            size_t ga = (size_t)(bm + row)*Kd + koff + col8;
            size_t gb = (size_t)(bn + row)*Kd + koff + col8;
            int so = row*AST + col8;
            *(uint4*)(Ash + so) = *(const uint4*)(Ah + ga);
            *(uint4*)(Asl + so) = *(const uint4*)(Al + ga);
            *(uint4*)(Bsh + so) = *(const uint4*)(Bh + gb);
            *(uint4*)(Bsl + so) = *(const uint4*)(Bl + gb);
        }
        __syncthreads();

        #pragma unroll
        for (int kk = 0; kk < KC; kk += 16) {
            uint32_t afh[2][4], afl[2][4], bfh[8][2], bfl[8][2];
            #pragma unroll
            for (int mt = 0; mt < 2; mt++) {
                int r0 = (wm + mt*16 + r)*AST + kk + 2*c;
                int r1 = r0 + 8*AST;
                afh[mt][0] = *(const uint32_t*)(Ash + r0);
                afh[mt][1] = *(const uint32_t*)(Ash + r1);
                afh[mt][2] = *(const uint32_t*)(Ash + r0 + 8);
                afh[mt][3] = *(const uint32_t*)(Ash + r1 + 8);
                afl[mt][0] = *(const uint32_t*)(Asl + r0);
                afl[mt][1] = *(const uint32_t*)(Asl + r1);
                afl[mt][2] = *(const uint32_t*)(Asl + r0 + 8);
                afl[mt][3] = *(const uint32_t*)(Asl + r1 + 8);
            }
            #pragma unroll
            for (int nt = 0; nt < 8; nt++) {
                int q = (wn + nt*8 + r)*AST + kk + 2*c;
                bfh[nt][0] = *(const uint32_t*)(Bsh + q);
                bfh[nt][1] = *(const uint32_t*)(Bsh + q + 8);
                bfl[nt][0] = *(const uint32_t*)(Bsl + q);
                bfl[nt][1] = *(const uint32_t*)(Bsl + q + 8);
            }
            #pragma unroll
            for (int mt = 0; mt < 2; mt++)
                #pragma unroll
                for (int nt = 0; nt < 8; nt++) {
                    mma16816(acc[mt][nt], afh[mt], bfh[nt]);
                    mma16816(acc[mt][nt], afh[mt], bfl[nt]);
                    mma16816(acc[mt][nt], afl[mt], bfh[nt]);
                }
        }
        __syncthreads();
    }

    // epilogue: fragments map to (rows r, r+8; cols 2c, 2c+1) per tile
    #pragma unroll
    for (int nt = 0; nt < 8; nt++) {
        int n = bn + wn + nt*8 + 2*c;
        float2 bv = *(const float2*)(bias + n);
        #pragma unroll
        for (int mt = 0; mt < 2; mt++) {
            #pragma unroll
            for (int half = 0; half < 2; half++) {
                int m = bm + wm + mt*16 + r + half*8;
                float v0 = acc[mt][nt][half*2+0] + bv.x;
                float v1 = acc[mt][nt][half*2+1] + bv.y;
                if (act) { v0 = silu_f(v0); v1 = silu_f(v1); }
                size_t idx = (size_t)m * Nd + n;
                if (Rres) { float2 rv = *(const float2*)(Rres + idx); v0 += rv.x; v1 += rv.y; }
                if (accum) {
                    float2 ov = *(const float2*)(Cout + idx);
                    v0 += ov.x; v1 += ov.y;
                }
                float2 w2; w2.x = v0; w2.y = v1;
                *(float2*)(Cout + idx) = w2;
            }
        }
    }
}

// ---------------- causal depthwise conv (K=4) + SiLU, reads xm from proj ----
__global__ void conv_silu_kernel(const float* __restrict__ proj,
                                 const float* __restrict__ cw,
                                 const float* __restrict__ cb,
                                 float* __restrict__ u)
{
    int g = blockIdx.x * blockDim.x + threadIdx.x;   // TT*EE
    if (g >= TT*EE) return;
    int e   = g % EE;
    int row = g / EE;
    int t   = row % LL;
    int b   = row / LL;
    float acc = cb[e];
    #pragma unroll
    for (int j = 0; j < 4; j++) {
        int tt = t - 3 + j;
        if (tt >= 0)
            acc = fmaf(proj[(size_t)(b*LL + tt)*(2*EE) + e], cw[e*4 + j], acc);
    }
    u[g] = silu_f(acc);
}

// ---------------- dbc = u @ xproj_w  (4096 x 1536 x 36 skinny GEMM) --------
__global__ __launch_bounds__(288) void dbc_kernel(const float* __restrict__ u,
                                                  const float* __restrict__ w,
                                                  float* __restrict__ dbc)
{
    __shared__ float su[EE];
    __shared__ float part[8][36];
    int row = blockIdx.x;
    for (int i = threadIdx.x; i < EE; i += 288) su[i] = u[(size_t)row*EE + i];
    __syncthreads();
    int j = threadIdx.x % 36, s = threadIdx.x / 36;   // 36 cols x 8 k-slices
    float acc = 0.0f;
    int k0 = s * (EE/8);
    for (int k = k0; k < k0 + EE/8; k++)
        acc = fmaf(su[k], w[k*36 + j], acc);
    part[s][j] = acc;
    __syncthreads();
    if (threadIdx.x < 36) {
        float t = 0.0f;
        #pragma unroll
        for (int ss = 0; ss < 8; ss++) t += part[ss][threadIdx.x];
        dbc[row*36 + threadIdx.x] = t;
    }
}

// ---------------- dt = softplus(dbc[:, :4] @ dt_w + dt_b) ------------------
__global__ void dt_kernel(const float* __restrict__ dbc,
                          const float* __restrict__ dtw,
                          const float* __restrict__ dtb,
                          float* __restrict__ dt)
{
    int g = blockIdx.x * blockDim.x + threadIdx.x;   // TT*EE
    if (g >= TT*EE) return;
    int e = g % EE, row = g / EE;
    float v = dtb[e];
    #pragma unroll
    for (int r = 0; r < 4; r++)
        v = fmaf(dbc[row*36 + r], dtw[r*EE + e], v);
    dt[g] = softplus_f(v);
}

// ---------------- scan pass A: per-chunk (prod dA, h'|h0=0) ----------------
__global__ void scan_chunk_kernel(const float* __restrict__ dtp,
                                  const float* __restrict__ up,
                                  const float* __restrict__ dbc,
                                  const float* __restrict__ A_log,
                                  float* __restrict__ cP, float* __restrict__ cH)
{
    int g = blockIdx.x * blockDim.x + threadIdx.x;
    int e = g % EE;
    int n = (g / EE) % NNS;
    int c = (g / (EE*NNS)) % NCH;
    int b =  g / (EE*NNS*NCH);
    float Aen = -expf(A_log[e*NNS + n]);
    float p = 1.0f, h = 0.0f;
    int rbase = b*LL + c*TCH;
    for (int t = 0; t < TCH; t++) {
        int row   = rbase + t;
        float dtv = dtp[(size_t)row*EE + e];
        float uv  = up [(size_t)row*EE + e];
        float bv  = dbc[row*36 + 4 + n];
        float dA  = expf(dtv * Aen);
        p *= dA;
        h = fmaf(h, dA, dtv * uv * bv);
    }
    size_t idx = ((size_t)((b*NCH + c)*NNS + n))*EE + e;
    cP[idx] = p; cH[idx] = h;
}

// ---------------- scan pass B: sequential carry across 16 chunks -----------
__global__ void scan_carry_kernel(const float* __restrict__ cP,
                                  const float* __restrict__ cH,
                                  float* __restrict__ hinit)
{
    int g = blockIdx.x * blockDim.x + threadIdx.x;   // BB*NNS*EE
    if (g >= BB*NNS*EE) return;
    int e = g % EE;
    int n = (g / EE) % NNS;
    int b =  g / (EE*NNS);
    float h = 0.0f;
    for (int c = 0; c < NCH; c++) {
        size_t idx = ((size_t)((b*NCH + c)*NNS + n))*EE + e;
        hinit[idx] = h;
        h = fmaf(cP[idx], h, cH[idx]);
    }
}

// ---------------- scan pass C: rescan with carry, reduce over n, gate ------
__global__ void scan_y_kernel(const float* __restrict__ dtp,
                              const float* __restrict__ up,
                              const float* __restrict__ dbc,
                              const float* __restrict__ hinit,
                              const float* __restrict__ A_log,
                              const float* __restrict__ Dv,
                              const float* __restrict__ proj,
                              float* __restrict__ y)
{
    int g = blockIdx.x * blockDim.x + threadIdx.x;
    int n = g % NNS;
    int e = (g / NNS) % EE;
    int c = (g / (NNS*EE)) % NCH;
    int b =  g / (NNS*EE*NCH);
    float Aen  = -expf(A_log[e*NNS + n]);
    float h    = hinit[((size_t)((b*NCH + c)*NNS + n))*EE + e];
    float Dval = Dv[e];
    int t0 = c*TCH;
    for (int t = t0; t < t0 + TCH; t++) {
        int row   = b*LL + t;
        float dtv = dtp[(size_t)row*EE + e];
        float uv  = up [(size_t)row*EE + e];
        float bv  = dbc[row*36 + 4  + n];
        float cv  = dbc[row*36 + 20 + n];
        h = fmaf(h, expf(dtv * Aen), dtv * uv * bv);
        float part = h * cv;
        part += __shfl_xor_sync(0xffffffffu, part, 8);
        part += __shfl_xor_sync(0xffffffffu, part, 4);
        part += __shfl_xor_sync(0xffffffffu, part, 2);
        part += __shfl_xor_sync(0xffffffffu, part, 1);
        if (n == 0) {
            float gate = proj[(size_t)row*(2*EE) + EE + e];
            y[(size_t)row*EE + e] = (part + uv*Dval) * sigmoid_f(gate);
        }
    }
}

// ---------------- small elementwise ----------------
__global__ void frac_add_kernel(float* __restrict__ hs, const float* __restrict__ acc, int n)
{
    int g = blockIdx.x * blockDim.x + threadIdx.x;
    if (g < n) hs[g] = fmaf(acc[g], 0.5f/3.0f, hs[g]);
}

// ---------------- host orchestration ----------------
extern "C" void kernel_launch(void* const* d_in, const int* in_sizes, int n_in,
                              void* d_out, int out_size)
{
    const int*   input_ids = (const int*)  d_in[0];
    const float* tok_emb   = (const float*)d_in[1];
    const float* pos_emb   = (const float*)d_in[2];
    const float* ln_w      = (const float*)d_in[3];
    const float* ln_b      = (const float*)d_in[4];
    const float* in_w      = (const float*)d_in[5];
    const float* in_b      = (const float*)d_in[6];
    const float* conv_w    = (const float*)d_in[7];
    const float* conv_b    = (const float*)d_in[8];
    const float* xproj_w   = (const float*)d_in[9];
    const float* dt_w      = (const float*)d_in[10];
    const float* dt_b      = (const float*)d_in[11];
    const float* A_log     = (const float*)d_in[12];
    const float* Dvec      = (const float*)d_in[13];
    const float* out_w     = (const float*)d_in[14];
    const float* out_b     = (const float*)d_in[15];
    const float* frac_w    = (const float*)d_in[16];
    const float* frac_b    = (const float*)d_in[17];
    const float* fln_w     = (const float*)d_in[18];
    const float* fln_b     = (const float*)d_in[19];
    float* outp = (float*)d_out;

    cudaFuncSetAttribute(mma_gemm, cudaFuncAttributeMaxDynamicSharedMemorySize,
                         MM_SMEM);

    float *hs, *x, *proj, *u, *dbc, *dt, *y, *cP, *cH, *hinit, *t1, *t2, *accb;
    cudaGetSymbolAddress((void**)&hs,    g_hs);
    cudaGetSymbolAddress((void**)&x,     g_x);
    cudaGetSymbolAddress((void**)&proj,  g_proj);
    cudaGetSymbolAddress((void**)&u,     g_u);
    cudaGetSymbolAddress((void**)&dbc,   g_dbc);
    cudaGetSymbolAddress((void**)&dt,    g_dt);
    cudaGetSymbolAddress((void**)&y,     g_y);
    cudaGetSymbolAddress((void**)&cP,    g_cP);
    cudaGetSymbolAddress((void**)&cH,    g_cH);
    cudaGetSymbolAddress((void**)&hinit, g_hinit);
    cudaGetSymbolAddress((void**)&t1,    g_t1);
    cudaGetSymbolAddress((void**)&t2,    g_t2);
    cudaGetSymbolAddress((void**)&accb,  g_accb);

    __nv_bfloat16 *Ah, *Al, *Ah2, *Al2, *Wth, *Wtl;
    cudaGetSymbolAddress((void**)&Ah,  g_Ah);
    cudaGetSymbolAddress((void**)&Al,  g_Al);
    cudaGetSymbolAddress((void**)&Ah2, g_Ah2);
    cudaGetSymbolAddress((void**)&Al2, g_Al2);
    cudaGetSymbolAddress((void**)&Wth, g_Wth);
    cudaGetSymbolAddress((void**)&Wtl, g_Wtl);

    const int EW  = TT*HH;
    const int EWE = TT*EE;
    const int SCAN_T = BB*NCH*NNS*EE;

    embed_kernel<<<(EW + 255)/256, 256>>>(input_ids, tok_emb, pos_emb, hs);

    for (int l = 0; l < NLAYER; l++) {
        // x = LN(hs)
        ln_kernel<<<TT, 256>>>(hs, ln_w + l*HH, ln_b + l*HH, x);
        // proj = x @ in_w + in_b  (4096 x 768 x 3072)
        convA_kernel<<<(EW + 255)/256, 256>>>(x, Ah, Al, EW);
        convW_kernel<<<dim3(2*EE/32, HH/32), 256>>>(
            in_w + (size_t)l*HH*2*EE, Wth, Wtl, HH, 2*EE);
        mma_gemm<<<dim3(2*EE/128, TT/128), 256, MM_SMEM>>>(
            Ah, Al, Wth, Wtl, in_b + l*2*EE, nullptr, proj, TT, HH, 2*EE, 0, 0);
        // u = silu(causal_dwconv(proj[:, :E]))
        conv_silu_kernel<<<(EWE + 255)/256, 256>>>(proj, conv_w + l*EE*4, conv_b + l*EE, u);
        // dbc = u @ xproj_w
        dbc_kernel<<<TT, 288>>>(u, xproj_w + (size_t)l*EE*36, dbc);
        // dt = softplus(dbc[:, :4] @ dt_w + dt_b)
        dt_kernel<<<(EWE + 255)/256, 256>>>(dbc, dt_w + l*RRK*EE, dt_b + l*EE, dt);
        // chunked selective scan
        scan_chunk_kernel<<<SCAN_T/256, 256>>>(dt, u, dbc, A_log + (size_t)l*EE*NNS, cP, cH);
        scan_carry_kernel<<<(BB*NNS*EE + 255)/256, 256>>>(cP, cH, hinit);
        scan_y_kernel<<<SCAN_T/256, 256>>>(dt, u, dbc, hinit,
            A_log + (size_t)l*EE*NNS, Dvec + l*EE, proj, y);
        // hs = y @ out_w + out_b + hs  (residual fused)  (4096 x 1536 x 768)
        convA_kernel<<<(EWE + 255)/256, 256>>>(y, Ah, Al, EWE);
        convW_kernel<<<dim3(HH/32, EE/32), 256>>>(
            out_w + (size_t)l*EE*HH, Wth, Wtl, EE, HH);
        mma_gemm<<<dim3(HH/128, TT/128), 256, MM_SMEM>>>(
            Ah, Al, Wth, Wtl, out_b + l*HH, hs, hs, TT, EE, HH, 0, 0);
        // fractal refinement: acc = sum_i silu^3(hs; W_i); hs += acc/6
        convA_kernel<<<(EW + 255)/256, 256>>>(hs, Ah2, Al2, EW);   // shared across branches
        for (int i = 0; i < CC; i++) {
            const float* Wp = frac_w + (size_t)(l*CC + i)*HH*HH;
            const float* bp = frac_b + (size_t)(l*CC + i)*HH;
            convW_kernel<<<dim3(HH/32, HH/32), 256>>>(Wp, Wth, Wtl, HH, HH);
            mma_gemm<<<dim3(HH/128, TT/128), 256, MM_SMEM>>>(
                Ah2, Al2, Wth, Wtl, bp, nullptr, t1, TT, HH, HH, 1, 0);
            convA_kernel<<<(EW + 255)/256, 256>>>(t1, Ah, Al, EW);
            mma_gemm<<<dim3(HH/128, TT/128), 256, MM_SMEM>>>(
                Ah, Al, Wth, Wtl, bp, nullptr, t2, TT, HH, HH, 1, 0);
            convA_kernel<<<(EW + 255)/256, 256>>>(t2, Ah, Al, EW);
            mma_gemm<<<dim3(HH/128, TT/128), 256, MM_SMEM>>>(
                Ah, Al, Wth, Wtl, bp, nullptr, accb, TT, HH, HH, 1, (i > 0) ? 1 : 0);
        }
        frac_add_kernel<<<(EW + 255)/256, 256>>>(hs, accb, EW);
    }

    // final layernorm -> output (float32)
    ln_kernel<<<TT, 256>>>(hs, fln_w, fln_b, outp);
    (void)in_sizes; (void)n_in; (void)out_size;
}

// round 14
// speedup vs baseline: 1.6235x; 1.0117x over previous
#include <cuda_runtime.h>
#include <cuda_bf16.h>
#include <math.h>
#include <stdint.h>

// ---------------- problem constants (fixed by the reference) ----------------
#define BB 2
#define LL 2048
#define HH 768
#define EE 1536
#define NNS 16           // state dim N
#define RRK 4            // dt rank R
#define CC 3
#define NLAYER 8
#define TT (BB*LL)       // 4096 rows
#define NCH 16           // scan chunks per sequence
#define TCH (LL/NCH)     // 128 steps per chunk

// ---------------- scratch (device globals: no runtime allocation) ----------
__device__ float g_hs  [TT*HH];
__device__ float g_proj[TT*2*EE];
__device__ float g_u   [TT*EE];
__device__ float g_dbc [TT*36];
__device__ float g_dt  [TT*EE];
__device__ float g_cP   [BB*NCH*NNS*EE];
__device__ float g_cH   [BB*NCH*NNS*EE];
__device__ float g_hinit[BB*NCH*NNS*EE];
__device__ float g_accb[TT*HH];

// bf16 hi/lo split buffers for tensor-core GEMM operands
__device__ __nv_bfloat16 g_Ah [TT*EE];   // activations (max K = 1536)
__device__ __nv_bfloat16 g_Al [TT*EE];
__device__ __nv_bfloat16 g_Ah2[TT*HH];   // hs splits (fractal input, reused)
__device__ __nv_bfloat16 g_Al2[TT*HH];
__device__ __nv_bfloat16 g_Ah3[TT*HH];   // t2 splits
__device__ __nv_bfloat16 g_Al3[TT*HH];
__device__ __nv_bfloat16 g_Wth[2*EE*HH]; // transposed weight [N,K], max 3072*768
__device__ __nv_bfloat16 g_Wtl[2*EE*HH];

// ---------------- helpers ----------------
__device__ __forceinline__ float silu_f(float v)    { return v / (1.0f + expf(-v)); }
__device__ __forceinline__ float sigmoid_f(float v) { return 1.0f / (1.0f + expf(-v)); }
__device__ __forceinline__ float softplus_f(float v){ return (v > 20.0f) ? v : log1pf(expf(v)); }

// mma.sync m16n8k16 bf16 -> fp32 accum (portable PTX)
__device__ __forceinline__ void mma16816(float* d, const uint32_t* a, const uint32_t* b)
{
    asm volatile(
        "mma.sync.aligned.m16n8k16.row.col.f32.bf16.bf16.f32 "
        "{%0,%1,%2,%3}, {%4,%5,%6,%7}, {%8,%9}, {%0,%1,%2,%3};"
        : "+f"(d[0]), "+f"(d[1]), "+f"(d[2]), "+f"(d[3])
        : "r"(a[0]), "r"(a[1]), "r"(a[2]), "r"(a[3]), "r"(b[0]), "r"(b[1]));
}
__device__ __forceinline__ void ldsm4(uint32_t* r, const __nv_bfloat16* p)
{
    uint32_t sa = (uint32_t)__cvta_generic_to_shared(p);
    asm volatile("ldmatrix.sync.aligned.m8n8.x4.shared.b16 {%0,%1,%2,%3}, [%4];"
                 : "=r"(r[0]), "=r"(r[1]), "=r"(r[2]), "=r"(r[3]) : "r"(sa));
}
__device__ __forceinline__ void cpa16(__nv_bfloat16* s, const __nv_bfloat16* g)
{
    uint32_t sa = (uint32_t)__cvta_generic_to_shared(s);
    asm volatile("cp.async.cg.shared.global [%0], [%1], 16;" :: "r"(sa), "l"(g));
}
__device__ __forceinline__ void split_store(__nv_bfloat16* Oh, __nv_bfloat16* Ol,
                                            size_t idx, float v0, float v1)
{
    __nv_bfloat16 h0 = __float2bfloat16(v0), h1 = __float2bfloat16(v1);
    __nv_bfloat162 hv; hv.x = h0; hv.y = h1;
    *(__nv_bfloat162*)(Oh + idx) = hv;
    __nv_bfloat162 lv;
    lv.x = __float2bfloat16(v0 - __bfloat162float(h0));
    lv.y = __float2bfloat16(v1 - __bfloat162float(h1));
    *(__nv_bfloat162*)(Ol + idx) = lv;
}

// ---------------- embedding ----------------
__global__ void embed_kernel(const int* __restrict__ ids,
                             const float* __restrict__ tok,
                             const float* __restrict__ pos,
                             float* __restrict__ hs)
{
    int g = blockIdx.x * blockDim.x + threadIdx.x;   // TT*HH
    if (g >= TT*HH) return;
    int h   = g % HH;
    int row = g / HH;
    int t   = row % LL;
    hs[g] = tok[(size_t)ids[row]*HH + h] + pos[(size_t)t*HH + h];
}

// ---------------- layernorm; optional float out and/or bf16 hi/lo split ----
__global__ __launch_bounds__(256) void ln_kernel(const float* __restrict__ in,
                                                 const float* __restrict__ w,
                                                 const float* __restrict__ b,
                                                 float* __restrict__ out,
                                                 __nv_bfloat16* __restrict__ oh,
                                                 __nv_bfloat16* __restrict__ ol)
{
    __shared__ float red[256];
    int row = blockIdx.x, tid = threadIdx.x;
    const float* x = in + (size_t)row*HH;
    float v0 = x[tid], v1 = x[tid+256], v2 = x[tid+512];
    red[tid] = v0 + v1 + v2;
    __syncthreads();
    #pragma unroll
    for (int s = 128; s > 0; s >>= 1) { if (tid < s) red[tid] += red[tid+s]; __syncthreads(); }
    float mean = red[0] * (1.0f/768.0f);
    __syncthreads();
    float d0 = v0-mean, d1 = v1-mean, d2 = v2-mean;
    red[tid] = d0*d0 + d1*d1 + d2*d2;
    __syncthreads();
    #pragma unroll
    for (int s = 128; s > 0; s >>= 1) { if (tid < s) red[tid] += red[tid+s]; __syncthreads(); }
    float inv = rsqrtf(red[0] * (1.0f/768.0f) + 1e-5f);
    size_t base = (size_t)row*HH;
    #pragma unroll
    for (int q = 0; q < 3; q++) {
        float dd = (q == 0) ? d0 : (q == 1) ? d1 : d2;
        int h = tid + q*256;
        float vv = dd*inv*w[h] + b[h];
        if (out) out[base + h] = vv;
        if (oh) {
            __nv_bfloat16 hb = __float2bfloat16(vv);
            oh[base + h] = hb;
            ol[base + h] = __float2bfloat16(vv - __bfloat162float(hb));
        }
    }
}

// ---------------- weight transpose + split: W[K,N] -> Wt[N,K] hi/lo --------
__global__ __launch_bounds__(256) void convW_kernel(const float* __restrict__ W,
                                                    __nv_bfloat16* __restrict__ Wth,
                                                    __nv_bfloat16* __restrict__ Wtl,
                                                    int Kd, int Nd)
{
    __shared__ float tile[32][33];
    int kb = blockIdx.y*32, nb = blockIdx.x*32;
    int tx = threadIdx.x & 31, ty = threadIdx.x >> 5;   // 32x8
    #pragma unroll
    for (int r = 0; r < 32; r += 8)
        tile[ty+r][tx] = W[(size_t)(kb+ty+r)*Nd + nb+tx];
    __syncthreads();
    #pragma unroll
    for (int r = 0; r < 32; r += 8) {
        int n = nb + ty + r, k = kb + tx;
        float v = tile[tx][ty+r];
        __nv_bfloat16 h = __float2bfloat16(v);
        Wth[(size_t)n*Kd + k] = h;
        Wtl[(size_t)n*Kd + k] = __float2bfloat16(v - __bfloat162float(h));
    }
}

// ---------------- tensor-core split-bf16 GEMM: cp.async pipelined ----------
// C = act(A*W + bias) [+res] [accum] ; optional bf16 hi/lo split output.
// A (Ah,Al) [M,K] bf16 row-major; W (Bh,Bl) [N,K] bf16 row-major.
// D = Ah*Bh^T + Ah*Bl^T + Al*Bh^T, fp32 accumulate.
// Block 128x128, 8 warps (4x2), warp tile 32x64, K-chunk 32, 2-stage pipeline.
// M%128==0, N%128==0, K%32==0.
#define KC  32
#define AST 40                         // smem row stride (bf16): conflict-free
#define TILE_E (128*AST)               // elems per tile
#define STAGE_E (4*TILE_E)             // 4 tiles per stage
#define MM_SMEM (2*STAGE_E*2)          // bytes (2 stages) = 81920

__global__ __launch_bounds__(256, 2) void mma_gemm(
    const __nv_bfloat16* __restrict__ Ah, const __nv_bfloat16* __restrict__ Al,
    const __nv_bfloat16* __restrict__ Bh, const __nv_bfloat16* __restrict__ Bl,
    const float* __restrict__ bias, const float* __restrict__ Rres,
    float* __restrict__ Cout,
    __nv_bfloat16* __restrict__ Oh, __nv_bfloat16* __restrict__ Ol,
    int M, int Kd, int Nd, int act, int accum)
{
    extern __shared__ __align__(16) __nv_bfloat16 sm[];
    const int tid = threadIdx.x, wid = tid >> 5, lane = tid & 31;
    const int bm = blockIdx.y*128, bn = blockIdx.x*128;
    const int wm = (wid & 3)*32, wn = (wid >> 2)*64;
    const int r = lane >> 2, c = lane & 3;

    float acc[2][8][4];
    #pragma unroll
    for (int mt = 0; mt < 2; mt++)
        #pragma unroll
        for (int nt = 0; nt < 8; nt++)
            #pragma unroll
            for (int j = 0; j < 4; j++) acc[mt][nt][j] = 0.0f;

    // fill mapping: 512 uint4 per tile, 256 threads x 2
    const int frow0 = tid >> 2, fcol = (tid & 3)*8;

    auto issue_fill = [&](int stage, int kc) {
        const size_t koff = (size_t)kc * KC;
        __nv_bfloat16* S = sm + stage*STAGE_E;
        #pragma unroll
        for (int i = 0; i < 2; i++) {
            int row = frow0 + i*64;
            int so = row*AST + fcol;
            size_t ga = (size_t)(bm + row)*Kd + koff + fcol;
            size_t gb = (size_t)(bn + row)*Kd + koff + fcol;
            cpa16(S + so,            Ah + ga);
            cpa16(S + TILE_E + so,   Al + ga);
            cpa16(S + 2*TILE_E + so, Bh + gb);
            cpa16(S + 3*TILE_E + so, Bl + gb);
        }
        asm volatile("cp.async.commit_group;" ::: "memory");
    };

    const int nkc = Kd / KC;
    issue_fill(0, 0);
    for (int kc = 0; kc < nkc; kc++) {
        if (kc + 1 < nkc) {
            issue_fill((kc + 1) & 1, kc + 1);
            asm volatile("cp.async.wait_group 1;" ::: "memory");
        } else {
            asm volatile("cp.async.wait_group 0;" ::: "memory");
        }
        __syncthreads();
        const __nv_bfloat16* S   = sm + (kc & 1)*STAGE_E;
        const __nv_bfloat16* Ash = S;
        const __nv_bfloat16* Asl = S + TILE_E;
        const __nv_bfloat16* Bsh = S + 2*TILE_E;
        const __nv_bfloat16* Bsl = S + 3*TILE_E;

        #pragma unroll
        for (int kk = 0; kk < KC; kk += 16) {
            uint32_t afh[2][4], afl[2][4];
            #pragma unroll
            for (int mt = 0; mt < 2; mt++) {
                int ae = (wm + mt*16 + (lane & 15))*AST + kk + ((lane >> 4)*8);
                ldsm4(afh[mt], Ash + ae);
                ldsm4(afl[mt], Asl + ae);
            }
            #pragma unroll
            for (int nt2 = 0; nt2 < 4; nt2++) {
                int be = (wn + nt2*16 + ((lane >> 4)*8) + (lane & 7))*AST
                         + kk + (((lane >> 3) & 1)*8);
                uint32_t bh[4], bl[4];
                ldsm4(bh, Bsh + be);
                ldsm4(bl, Bsl + be);
                #pragma unroll
                for (int h = 0; h < 2; h++) {
                    #pragma unroll
                    for (int mt = 0; mt < 2; mt++) {
                        float* d = acc[mt][nt2*2 + h];
                        mma16816(d, afh[mt], bh + 2*h);
                        mma16816(d, afh[mt], bl + 2*h);
                        mma16816(d, afl[mt], bh + 2*h);
                    }
                }
            }
        }
        __syncthreads();
    }

    // epilogue: fragment (rows r, r+8; cols 2c, 2c+1)
    #pragma unroll
    for (int nt = 0; nt < 8; nt++) {
        int n = bn + wn + nt*8 + 2*c;
        float2 bv = *(const float2*)(bias + n);
        #pragma unroll
        for (int mt = 0; mt < 2; mt++) {
            #pragma unroll
            for (int half = 0; half < 2; half++) {
                int m = bm + wm + mt*16 + r + half*8;
                float v0 = acc[mt][nt][half*2+0] + bv.x;
                float v1 = acc[mt][nt][half*2+1] + bv.y;
                if (act) { v0 = silu_f(v0); v1 = silu_f(v1); }
                size_t idx = (size_t)m * Nd + n;
                if (Rres) { float2 rv = *(const float2*)(Rres + idx); v0 += rv.x; v1 += rv.y; }
                if (Cout) {
                    if (accum) {
                        float2 ov = *(const float2*)(Cout + idx);
                        v0 += ov.x; v1 += ov.y;
                    }
                    float2 w2; w2.x = v0; w2.y = v1;
                    *(float2*)(Cout + idx) = w2;
                }
                if (Oh) split_store(Oh, Ol, idx, v0, v1);
            }
        }
    }
}

// ---------------- causal depthwise conv (K=4) + SiLU, reads xm from proj ----
__global__ void conv_silu_kernel(const float* __restrict__ proj,
                                 const float* __restrict__ cw,
                                 const float* __restrict__ cb,
                                 float* __restrict__ u)
{
    int g = blockIdx.x * blockDim.x + threadIdx.x;   // TT*EE
    if (g >= TT*EE) return;
    int e   = g % EE;
    int row = g / EE;
    int t   = row % LL;
    int b   = row / LL;
    float acc = cb[e];
    #pragma unroll
    for (int j = 0; j < 4; j++) {
        int tt = t - 3 + j;
        if (tt >= 0)
            acc = fmaf(proj[(size_t)(b*LL + tt)*(2*EE) + e], cw[e*4 + j], acc);
    }
    u[g] = silu_f(acc);
}

// ---------------- dbc = u @ xproj_w  (4096 x 1536 x 36 skinny GEMM) --------
__global__ __launch_bounds__(288) void dbc_kernel(const float* __restrict__ u,
                                                  const float* __restrict__ w,
                                                  float* __restrict__ dbc)
{
    __shared__ float su[EE];
    __shared__ float part[8][36];
    int row = blockIdx.x;
    for (int i = threadIdx.x; i < EE; i += 288) su[i] = u[(size_t)row*EE + i];
    __syncthreads();
    int j = threadIdx.x % 36, s = threadIdx.x / 36;   // 36 cols x 8 k-slices
    float acc = 0.0f;
    int k0 = s * (EE/8);
    for (int k = k0; k < k0 + EE/8; k++)
        acc = fmaf(su[k], w[k*36 + j], acc);
    part[s][j] = acc;
    __syncthreads();
    if (threadIdx.x < 36) {
        float t = 0.0f;
        #pragma unroll
        for (int ss = 0; ss < 8; ss++) t += part[ss][threadIdx.x];
        dbc[row*36 + threadIdx.x] = t;
    }
}

// ---------------- dt = softplus(dbc[:, :4] @ dt_w + dt_b) ------------------
__global__ void dt_kernel(const float* __restrict__ dbc,
                          const float* __restrict__ dtw,
                          const float* __restrict__ dtb,
                          float* __restrict__ dt)
{
    int g = blockIdx.x * blockDim.x + threadIdx.x;   // TT*EE
    if (g >= TT*EE) return;
    int e = g % EE, row = g / EE;
    float v = dtb[e];
    #pragma unroll
    for (int r = 0; r < 4; r++)
        v = fmaf(dbc[row*36 + r], dtw[r*EE + e], v);
    dt[g] = softplus_f(v);
}

// ---------------- scan pass A: per-chunk (prod dA, h'|h0=0) ----------------
__global__ void scan_chunk_kernel(const float* __restrict__ dtp,
                                  const float* __restrict__ up,
                                  const float* __restrict__ dbc,
                                  const float* __restrict__ A_log,
                                  float* __restrict__ cP, float* __restrict__ cH)
{
    int g = blockIdx.x * blockDim.x + threadIdx.x;
    int e = g % EE;
    int n = (g / EE) % NNS;
    int c = (g / (EE*NNS)) % NCH;
    int b =  g / (EE*NNS*NCH);
    float Aen = -expf(A_log[e*NNS + n]);
    float p = 1.0f, h = 0.0f;
    int rbase = b*LL + c*TCH;
    for (int t = 0; t < TCH; t++) {
        int row   = rbase + t;
        float dtv = dtp[(size_t)row*EE + e];
        float uv  = up [(size_t)row*EE + e];
        float bv  = dbc[row*36 + 4 + n];
        float dA  = expf(dtv * Aen);
        p *= dA;
        h = fmaf(h, dA, dtv * uv * bv);
    }
    size_t idx = ((size_t)((b*NCH + c)*NNS + n))*EE + e;
    cP[idx] = p; cH[idx] = h;
}

// ---------------- scan pass B: sequential carry across 16 chunks -----------
__global__ void scan_carry_kernel(const float* __restrict__ cP,
                                  const float* __restrict__ cH,
                                  float* __restrict__ hinit)
{
    int g = blockIdx.x * blockDim.x + threadIdx.x;   // BB*NNS*EE
    if (g >= BB*NNS*EE) return;
    int e = g % EE;
    int n = (g / EE) % NNS;
    int b =  g / (EE*NNS);
    float h = 0.0f;
    for (int c = 0; c < NCH; c++) {
        size_t idx = ((size_t)((b*NCH + c)*NNS + n))*EE + e;
        hinit[idx] = h;
        h = fmaf(cP[idx], h, cH[idx]);
    }
}

// ---------------- scan pass C: rescan + gate; writes y as bf16 hi/lo -------
__global__ void scan_y_kernel(const float* __restrict__ dtp,
                              const float* __restrict__ up,
                              const float* __restrict__ dbc,
                              const float* __restrict__ hinit,
                              const float* __restrict__ A_log,
                              const float* __restrict__ Dv,
                              const float* __restrict__ proj,
                              __nv_bfloat16* __restrict__ yh,
                              __nv_bfloat16* __restrict__ yl)
{
    int g = blockIdx.x * blockDim.x + threadIdx.x;
    int n = g % NNS;
    int e = (g / NNS) % EE;
    int c = (g / (NNS*EE)) % NCH;
    int b =  g / (NNS*EE*NCH);
    float Aen  = -expf(A_log[e*NNS + n]);
    float h    = hinit[((size_t)((b*NCH + c)*NNS + n))*EE + e];
    float Dval = Dv[e];
    int t0 = c*TCH;
    for (int t = t0; t < t0 + TCH; t++) {
        int row   = b*LL + t;
        float dtv = dtp[(size_t)row*EE + e];
        float uv  = up [(size_t)row*EE + e];
        float bv  = dbc[row*36 + 4  + n];
        float cv  = dbc[row*36 + 20 + n];
        h = fmaf(h, expf(dtv * Aen), dtv * uv * bv);
        float part = h * cv;
        part += __shfl_xor_sync(0xffffffffu, part, 8);
        part += __shfl_xor_sync(0xffffffffu, part, 4);
        part += __shfl_xor_sync(0xffffffffu, part, 2);
        part += __shfl_xor_sync(0xffffffffu, part, 1);
        if (n == 0) {
            float gate = proj[(size_t)row*(2*EE) + EE + e];
            float yv = (part + uv*Dval) * sigmoid_f(gate);
            size_t yi = (size_t)row*EE + e;
            __nv_bfloat16 hb = __float2bfloat16(yv);
            yh[yi] = hb;
            yl[yi] = __float2bfloat16(yv - __bfloat162float(hb));
        }
    }
}

// ---------------- small elementwise ----------------
__global__ void frac_add_kernel(float* __restrict__ hs, const float* __restrict__ acc, int n)
{
    int g = blockIdx.x * blockDim.x + threadIdx.x;
    if (g < n) hs[g] = fmaf(acc[g], 0.5f/3.0f, hs[g]);
}

// ---------------- host orchestration ----------------
extern "C" void kernel_launch(void* const* d_in, const int* in_sizes, int n_in,
                              void* d_out, int out_size)
{
    const int*   input_ids = (const int*)  d_in[0];
    const float* tok_emb   = (const float*)d_in[1];
    const float* pos_emb   = (const float*)d_in[2];
    const float* ln_w      = (const float*)d_in[3];
    const float* ln_b      = (const float*)d_in[4];
    const float* in_w      = (const float*)d_in[5];
    const float* in_b      = (const float*)d_in[6];
    const float* conv_w    = (const float*)d_in[7];
    const float* conv_b    = (const float*)d_in[8];
    const float* xproj_w   = (const float*)d_in[9];
    const float* dt_w      = (const float*)d_in[10];
    const float* dt_b      = (const float*)d_in[11];
    const float* A_log     = (const float*)d_in[12];
    const float* Dvec      = (const float*)d_in[13];
    const float* out_w     = (const float*)d_in[14];
    const float* out_b     = (const float*)d_in[15];
    const float* frac_w    = (const float*)d_in[16];
    const float* frac_b    = (const float*)d_in[17];
    const float* fln_w     = (const float*)d_in[18];
    const float* fln_b     = (const float*)d_in[19];
    float* outp = (float*)d_out;

    cudaFuncSetAttribute(mma_gemm, cudaFuncAttributeMaxDynamicSharedMemorySize,
                         MM_SMEM);

    float *hs, *proj, *u, *dbc, *dt, *cP, *cH, *hinit, *accb;
    cudaGetSymbolAddress((void**)&hs,    g_hs);
    cudaGetSymbolAddress((void**)&proj,  g_proj);
    cudaGetSymbolAddress((void**)&u,     g_u);
    cudaGetSymbolAddress((void**)&dbc,   g_dbc);
    cudaGetSymbolAddress((void**)&dt,    g_dt);
    cudaGetSymbolAddress((void**)&cP,    g_cP);
    cudaGetSymbolAddress((void**)&cH,    g_cH);
    cudaGetSymbolAddress((void**)&hinit, g_hinit);
    cudaGetSymbolAddress((void**)&accb,  g_accb);

    __nv_bfloat16 *Ah, *Al, *Ah2, *Al2, *Ah3, *Al3, *Wth, *Wtl;
    cudaGetSymbolAddress((void**)&Ah,  g_Ah);
    cudaGetSymbolAddress((void**)&Al,  g_Al);
    cudaGetSymbolAddress((void**)&Ah2, g_Ah2);
    cudaGetSymbolAddress((void**)&Al2, g_Al2);
    cudaGetSymbolAddress((void**)&Ah3, g_Ah3);
    cudaGetSymbolAddress((void**)&Al3, g_Al3);
    cudaGetSymbolAddress((void**)&Wth, g_Wth);
    cudaGetSymbolAddress((void**)&Wtl, g_Wtl);

    const int EW  = TT*HH;
    const int EWE = TT*EE;
    const int SCAN_T = BB*NCH*NNS*EE;

    embed_kernel<<<(EW + 255)/256, 256>>>(input_ids, tok_emb, pos_emb, hs);

    for (int l = 0; l < NLAYER; l++) {
        // x = LN(hs) -> bf16 hi/lo only (feeds GEMM directly)
        ln_kernel<<<TT, 256>>>(hs, ln_w + l*HH, ln_b + l*HH, nullptr, Ah, Al);
        // proj = x @ in_w + in_b  (4096 x 768 x 3072)
        convW_kernel<<<dim3(2*EE/32, HH/32), 256>>>(
            in_w + (size_t)l*HH*2*EE, Wth, Wtl, HH, 2*EE);
        mma_gemm<<<dim3(2*EE/128, TT/128), 256, MM_SMEM>>>(
            Ah, Al, Wth, Wtl, in_b + l*2*EE, nullptr, proj, nullptr, nullptr,
            TT, HH, 2*EE, 0, 0);
        // u = silu(causal_dwconv(proj[:, :E]))
        conv_silu_kernel<<<(EWE + 255)/256, 256>>>(proj, conv_w + l*EE*4, conv_b + l*EE, u);
        // dbc = u @ xproj_w
        dbc_kernel<<<TT, 288>>>(u, xproj_w + (size_t)l*EE*36, dbc);
        // dt = softplus(dbc[:, :4] @ dt_w + dt_b)
        dt_kernel<<<(EWE + 255)/256, 256>>>(dbc, dt_w + l*RRK*EE, dt_b + l*EE, dt);
        // chunked selective scan; pass C emits y as bf16 splits (overwrites Ah/Al)
        scan_chunk_kernel<<<SCAN_T/256, 256>>>(dt, u, dbc, A_log + (size_t)l*EE*NNS, cP, cH);
        scan_carry_kernel<<<(BB*NNS*EE + 255)/256, 256>>>(cP, cH, hinit);
        scan_y_kernel<<<SCAN_T/256, 256>>>(dt, u, dbc, hinit,
            A_log + (size_t)l*EE*NNS, Dvec + l*EE, proj, Ah, Al);
        // hs = y @ out_w + out_b + hs; also emit hs splits for fractal input
        convW_kernel<<<dim3(HH/32, EE/32), 256>>>(
            out_w + (size_t)l*EE*HH, Wth, Wtl, EE, HH);
        mma_gemm<<<dim3(HH/128, TT/128), 256, MM_SMEM>>>(
            Ah, Al, Wth, Wtl, out_b + l*HH, hs, hs, Ah2, Al2,
            TT, EE, HH, 0, 0);
        // fractal refinement: acc = sum_i silu^3(hs; W_i); hs += acc/6
        for (int i = 0; i < CC; i++) {
            const float* Wp = frac_w + (size_t)(l*CC + i)*HH*HH;
            const float* bp = frac_b + (size_t)(l*CC + i)*HH;
            convW_kernel<<<dim3(HH/32, HH/32), 256>>>(Wp, Wth, Wtl, HH, HH);
            // t1 = silu(hs @ W + b)   -> bf16 splits only
            mma_gemm<<<dim3(HH/128, TT/128), 256, MM_SMEM>>>(
                Ah2, Al2, Wth, Wtl, bp, nullptr, nullptr, Ah, Al,
                TT, HH, HH, 1, 0);
            // t2 = silu(t1 @ W + b)   -> bf16 splits only
            mma_gemm<<<dim3(HH/128, TT/128), 256, MM_SMEM>>>(
                Ah, Al, Wth, Wtl, bp, nullptr, nullptr, Ah3, Al3,
                TT, HH, HH, 1, 0);
            // accb (+)= silu(t2 @ W + b)
            mma_gemm<<<dim3(HH/128, TT/128), 256, MM_SMEM>>>(
                Ah3, Al3, Wth, Wtl, bp, nullptr, accb, nullptr, nullptr,
                TT, HH, HH, 1, (i > 0) ? 1 : 0);
        }
        frac_add_kernel<<<(EW + 255)/256, 256>>>(hs, accb, EW);
    }

    // final layernorm -> output (float32)
    ln_kernel<<<TT, 256>>>(hs, fln_w, fln_b, outp, nullptr, nullptr);
    (void)in_sizes; (void)n_in; (void)out_size;
}

// round 15
// speedup vs baseline: 1.8208x; 1.1215x over previous
#include <cuda_runtime.h>
#include <cuda_bf16.h>
#include <math.h>
#include <stdint.h>

// ---------------- problem constants (fixed by the reference) ----------------
#define BB 2
#define LL 2048
#define HH 768
#define EE 1536
#define NNS 16           // state dim N
#define RRK 4            // dt rank R
#define CC 3
#define NLAYER 8
#define TT (BB*LL)       // 4096 rows
#define NCH 16           // scan chunks per sequence
#define TCH (LL/NCH)     // 128 steps per chunk

// ---------------- scratch (device globals: no runtime allocation) ----------
__device__ float g_hs  [TT*HH];
__device__ float g_proj[TT*2*EE];
__device__ float g_u   [TT*EE];
__device__ float g_dbc [TT*36];
__device__ float g_dt  [TT*EE];
__device__ float g_cP   [BB*NCH*NNS*EE];
__device__ float g_cH   [BB*NCH*NNS*EE];
__device__ float g_hinit[BB*NCH*NNS*EE];
__device__ float g_t3  [CC*TT*HH];       // fractal 3rd-step outputs per branch

// bf16 hi/lo split buffers (activations)
__device__ __nv_bfloat16 g_Ah [TT*EE];   // layer activations (max K = 1536)
__device__ __nv_bfloat16 g_Al [TT*EE];
__device__ __nv_bfloat16 g_Ah2[TT*HH];   // hs splits (fractal input, z-shared)
__device__ __nv_bfloat16 g_Al2[TT*HH];
__device__ __nv_bfloat16 g_F1h[CC*TT*HH], g_F1l[CC*TT*HH];  // fractal t1 per branch
__device__ __nv_bfloat16 g_F2h[CC*TT*HH], g_F2l[CC*TT*HH];  // fractal t2 per branch

// precomputed weight splits, transposed to [N,K] per layer (all layers upfront)
__device__ __nv_bfloat16 g_Wih[(size_t)NLAYER*HH*2*EE];
__device__ __nv_bfloat16 g_Wil[(size_t)NLAYER*HH*2*EE];
__device__ __nv_bfloat16 g_Woh[(size_t)NLAYER*EE*HH];
__device__ __nv_bfloat16 g_Wol[(size_t)NLAYER*EE*HH];
__device__ __nv_bfloat16 g_Wfh[(size_t)NLAYER*CC*HH*HH];
__device__ __nv_bfloat16 g_Wfl[(size_t)NLAYER*CC*HH*HH];

// ---------------- helpers ----------------
__device__ __forceinline__ float silu_f(float v)    { return v / (1.0f + expf(-v)); }
__device__ __forceinline__ float sigmoid_f(float v) { return 1.0f / (1.0f + expf(-v)); }
__device__ __forceinline__ float softplus_f(float v){ return (v > 20.0f) ? v : log1pf(expf(v)); }

__device__ __forceinline__ void mma16816(float* d, const uint32_t* a, const uint32_t* b)
{
    asm volatile(
        "mma.sync.aligned.m16n8k16.row.col.f32.bf16.bf16.f32 "
        "{%0,%1,%2,%3}, {%4,%5,%6,%7}, {%8,%9}, {%0,%1,%2,%3};"
        : "+f"(d[0]), "+f"(d[1]), "+f"(d[2]), "+f"(d[3])
        : "r"(a[0]), "r"(a[1]), "r"(a[2]), "r"(a[3]), "r"(b[0]), "r"(b[1]));
}
__device__ __forceinline__ void ldsm4(uint32_t* r, const __nv_bfloat16* p)
{
    uint32_t sa = (uint32_t)__cvta_generic_to_shared(p);
    asm volatile("ldmatrix.sync.aligned.m8n8.x4.shared.b16 {%0,%1,%2,%3}, [%4];"
                 : "=r"(r[0]), "=r"(r[1]), "=r"(r[2]), "=r"(r[3]) : "r"(sa));
}
__device__ __forceinline__ void cpa16(__nv_bfloat16* s, const __nv_bfloat16* g)
{
    uint32_t sa = (uint32_t)__cvta_generic_to_shared(s);
    asm volatile("cp.async.cg.shared.global [%0], [%1], 16;" :: "r"(sa), "l"(g));
}
__device__ __forceinline__ void split_store(__nv_bfloat16* Oh, __nv_bfloat16* Ol,
                                            size_t idx, float v0, float v1)
{
    __nv_bfloat16 h0 = __float2bfloat16(v0), h1 = __float2bfloat16(v1);
    __nv_bfloat162 hv; hv.x = h0; hv.y = h1;
    *(__nv_bfloat162*)(Oh + idx) = hv;
    __nv_bfloat162 lv;
    lv.x = __float2bfloat16(v0 - __bfloat162float(h0));
    lv.y = __float2bfloat16(v1 - __bfloat162float(h1));
    *(__nv_bfloat162*)(Ol + idx) = lv;
}

// ---------------- embedding ----------------
__global__ void embed_kernel(const int* __restrict__ ids,
                             const float* __restrict__ tok,
                             const float* __restrict__ pos,
                             float* __restrict__ hs)
{
    int g = blockIdx.x * blockDim.x + threadIdx.x;   // TT*HH
    if (g >= TT*HH) return;
    int h   = g % HH;
    int row = g / HH;
    int t   = row % LL;
    hs[g] = tok[(size_t)ids[row]*HH + h] + pos[(size_t)t*HH + h];
}

// ---------------- layernorm; optional float out and/or bf16 hi/lo split ----
__global__ __launch_bounds__(256) void ln_kernel(const float* __restrict__ in,
                                                 const float* __restrict__ w,
                                                 const float* __restrict__ b,
                                                 float* __restrict__ out,
                                                 __nv_bfloat16* __restrict__ oh,
                                                 __nv_bfloat16* __restrict__ ol)
{
    __shared__ float red[256];
    int row = blockIdx.x, tid = threadIdx.x;
    const float* x = in + (size_t)row*HH;
    float v0 = x[tid], v1 = x[tid+256], v2 = x[tid+512];
    red[tid] = v0 + v1 + v2;
    __syncthreads();
    #pragma unroll
    for (int s = 128; s > 0; s >>= 1) { if (tid < s) red[tid] += red[tid+s]; __syncthreads(); }
    float mean = red[0] * (1.0f/768.0f);
    __syncthreads();
    float d0 = v0-mean, d1 = v1-mean, d2 = v2-mean;
    red[tid] = d0*d0 + d1*d1 + d2*d2;
    __syncthreads();
    #pragma unroll
    for (int s = 128; s > 0; s >>= 1) { if (tid < s) red[tid] += red[tid+s]; __syncthreads(); }
    float inv = rsqrtf(red[0] * (1.0f/768.0f) + 1e-5f);
    size_t base = (size_t)row*HH;
    #pragma unroll
    for (int q = 0; q < 3; q++) {
        float dd = (q == 0) ? d0 : (q == 1) ? d1 : d2;
        int h = tid + q*256;
        float vv = dd*inv*w[h] + b[h];
        if (out) out[base + h] = vv;
        if (oh) {
            __nv_bfloat16 hb = __float2bfloat16(vv);
            oh[base + h] = hb;
            ol[base + h] = __float2bfloat16(vv - __bfloat162float(hb));
        }
    }
}

// ---------------- weight transpose + split: W[K,N] -> Wt[N,K] hi/lo --------
// blockIdx.z selects a weight matrix (offset z*Kd*Nd on both src and dst).
__global__ __launch_bounds__(256) void convW_kernel(const float* __restrict__ W,
                                                    __nv_bfloat16* __restrict__ Wth,
                                                    __nv_bfloat16* __restrict__ Wtl,
                                                    int Kd, int Nd)
{
    __shared__ float tile[32][33];
    size_t zo = (size_t)blockIdx.z * Kd * Nd;
    W += zo; Wth += zo; Wtl += zo;
    int kb = blockIdx.y*32, nb = blockIdx.x*32;
    int tx = threadIdx.x & 31, ty = threadIdx.x >> 5;   // 32x8
    #pragma unroll
    for (int r = 0; r < 32; r += 8)
        tile[ty+r][tx] = W[(size_t)(kb+ty+r)*Nd + nb+tx];
    __syncthreads();
    #pragma unroll
    for (int r = 0; r < 32; r += 8) {
        int n = nb + ty + r, k = kb + tx;
        float v = tile[tx][ty+r];
        __nv_bfloat16 h = __float2bfloat16(v);
        Wth[(size_t)n*Kd + k] = h;
        Wtl[(size_t)n*Kd + k] = __float2bfloat16(v - __bfloat162float(h));
    }
}

// ---------------- tensor-core split-bf16 GEMM: 3-stage cp.async ------------
// C = act(A*W + bias) [+res] [accum] ; optional bf16 hi/lo split output.
// A (Ah,Al) [M,K] bf16 row-major; W (Bh,Bl) [N,K] bf16 row-major.
// D = Ah*Bh^T + Ah*Bl^T + Al*Bh^T, fp32 accumulate.
// Block 128(M)x64(N), 8 warps (4m x 2n), warp tile 32x32, KC=32, 3 stages.
// blockIdx.z batches independent GEMMs via az/wz/bz/oz element strides.
// M%128==0, N%64==0, K%32==0, K/32 >= 3.
#define KC  32
#define AST 40                          // smem row stride (bf16): conflict-free
#define TILE_A (128*AST)
#define TILE_B (64*AST)
#define STAGE_E (2*TILE_A + 2*TILE_B)   // 15360 elems
#define MM_SMEM (3*STAGE_E*2)           // 92160 bytes

__global__ __launch_bounds__(256, 2) void mma_gemm(
    const __nv_bfloat16* __restrict__ Ah, const __nv_bfloat16* __restrict__ Al,
    const __nv_bfloat16* __restrict__ Bh, const __nv_bfloat16* __restrict__ Bl,
    const float* __restrict__ bias, const float* __restrict__ Rres,
    float* __restrict__ Cout,
    __nv_bfloat16* __restrict__ Oh, __nv_bfloat16* __restrict__ Ol,
    int Kd, int Nd, int act, int accum,
    long az, long wz, int bz, long oz)
{
    extern __shared__ __align__(16) __nv_bfloat16 sm[];
    const int tid = threadIdx.x, wid = tid >> 5, lane = tid & 31;
    const int bm = blockIdx.y*128, bn = blockIdx.x*64;
    const int wm = (wid & 3)*32, wn = (wid >> 2)*32;
    const int r = lane >> 2, c = lane & 3;
    const int z = blockIdx.z;

    Ah += (size_t)az*z; Al += (size_t)az*z;
    Bh += (size_t)wz*z; Bl += (size_t)wz*z;
    bias += (size_t)bz*z;

    float acc[2][4][4];
    #pragma unroll
    for (int mt = 0; mt < 2; mt++)
        #pragma unroll
        for (int nt = 0; nt < 4; nt++)
            #pragma unroll
            for (int j = 0; j < 4; j++) acc[mt][nt][j] = 0.0f;

    auto issue_fill = [&](int stage, int kc) {
        const size_t koff = (size_t)kc * KC;
        __nv_bfloat16* S = sm + stage*STAGE_E;
        #pragma unroll
        for (int i = 0; i < 2; i++) {
            int q = tid + i*256;              // 0..511 -> A rows
            int row = q >> 2, col = (q & 3)*8;
            int so = row*AST + col;
            size_t ga = (size_t)(bm + row)*Kd + koff + col;
            cpa16(S + so,          Ah + ga);
            cpa16(S + TILE_A + so, Al + ga);
        }
        {
            int row = tid >> 2, col = (tid & 3)*8;   // B rows 0..63
            int so = row*AST + col;
            size_t gb = (size_t)(bn + row)*Kd + koff + col;
            cpa16(S + 2*TILE_A + so,          Bh + gb);
            cpa16(S + 2*TILE_A + TILE_B + so, Bl + gb);
        }
        asm volatile("cp.async.commit_group;" ::: "memory");
    };

    const int nkc = Kd / KC;
    issue_fill(0, 0);
    issue_fill(1, 1);
    int stage = 0;
    for (int kc = 0; kc < nkc; kc++) {
        if (kc + 1 < nkc) { asm volatile("cp.async.wait_group 1;" ::: "memory"); }
        else              { asm volatile("cp.async.wait_group 0;" ::: "memory"); }
        __syncthreads();
        if (kc + 2 < nkc) {
            int ns = stage + 2; if (ns >= 3) ns -= 3;
            issue_fill(ns, kc + 2);
        }
        const __nv_bfloat16* S   = sm + stage*STAGE_E;
        const __nv_bfloat16* Ash = S;
        const __nv_bfloat16* Asl = S + TILE_A;
        const __nv_bfloat16* Bsh = S + 2*TILE_A;
        const __nv_bfloat16* Bsl = S + 2*TILE_A + TILE_B;

        #pragma unroll
        for (int kk = 0; kk < KC; kk += 16) {
            uint32_t afh[2][4], afl[2][4];
            #pragma unroll
            for (int mt = 0; mt < 2; mt++) {
                int ae = (wm + mt*16 + (lane & 15))*AST + kk + ((lane >> 4)*8);
                ldsm4(afh[mt], Ash + ae);
                ldsm4(afl[mt], Asl + ae);
            }
            #pragma unroll
            for (int nt2 = 0; nt2 < 2; nt2++) {
                int be = (wn + nt2*16 + ((lane >> 4)*8) + (lane & 7))*AST
                         + kk + (((lane >> 3) & 1)*8);
                uint32_t bh[4], bl[4];
                ldsm4(bh, Bsh + be);
                ldsm4(bl, Bsl + be);
                #pragma unroll
                for (int h = 0; h < 2; h++) {
                    #pragma unroll
                    for (int mt = 0; mt < 2; mt++) {
                        float* d = acc[mt][nt2*2 + h];
                        mma16816(d, afh[mt], bh + 2*h);
                        mma16816(d, afh[mt], bl + 2*h);
                        mma16816(d, afl[mt], bh + 2*h);
                    }
                }
            }
        }
        stage++; if (stage >= 3) stage = 0;
        // no trailing sync: next iteration's wait+sync protects stage reuse
    }

    // epilogue: fragment (rows r, r+8; cols 2c, 2c+1)
    #pragma unroll
    for (int nt = 0; nt < 4; nt++) {
        int n = bn + wn + nt*8 + 2*c;
        float2 bv = *(const float2*)(bias + n);
        #pragma unroll
        for (int mt = 0; mt < 2; mt++) {
            #pragma unroll
            for (int half = 0; half < 2; half++) {
                int m = bm + wm + mt*16 + r + half*8;
                float v0 = acc[mt][nt][half*2+0] + bv.x;
                float v1 = acc[mt][nt][half*2+1] + bv.y;
                if (act) { v0 = silu_f(v0); v1 = silu_f(v1); }
                size_t idx = (size_t)m * Nd + n + (size_t)oz*z;
                if (Rres) { float2 rv = *(const float2*)(Rres + idx); v0 += rv.x; v1 += rv.y; }
                if (Cout) {
                    if (accum) {
                        float2 ov = *(const float2*)(Cout + idx);
                        v0 += ov.x; v1 += ov.y;
                    }
                    float2 w2; w2.x = v0; w2.y = v1;
                    *(float2*)(Cout + idx) = w2;
                }
                if (Oh) split_store(Oh, Ol, idx, v0, v1);
            }
        }
    }
}

// ---------------- causal depthwise conv (K=4) + SiLU, reads xm from proj ----
__global__ void conv_silu_kernel(const float* __restrict__ proj,
                                 const float* __restrict__ cw,
                                 const float* __restrict__ cb,
                                 float* __restrict__ u)
{
    int g = blockIdx.x * blockDim.x + threadIdx.x;   // TT*EE
    if (g >= TT*EE) return;
    int e   = g % EE;
    int row = g / EE;
    int t   = row % LL;
    int b   = row / LL;
    float acc = cb[e];
    #pragma unroll
    for (int j = 0; j < 4; j++) {
        int tt = t - 3 + j;
        if (tt >= 0)
            acc = fmaf(proj[(size_t)(b*LL + tt)*(2*EE) + e], cw[e*4 + j], acc);
    }
    u[g] = silu_f(acc);
}

// ---------------- dbc = u @ xproj_w  (4096 x 1536 x 36 skinny GEMM) --------
__global__ __launch_bounds__(288) void dbc_kernel(const float* __restrict__ u,
                                                  const float* __restrict__ w,
                                                  float* __restrict__ dbc)
{
    __shared__ float su[EE];
    __shared__ float part[8][36];
    int row = blockIdx.x;
    for (int i = threadIdx.x; i < EE; i += 288) su[i] = u[(size_t)row*EE + i];
    __syncthreads();
    int j = threadIdx.x % 36, s = threadIdx.x / 36;   // 36 cols x 8 k-slices
    float acc = 0.0f;
    int k0 = s * (EE/8);
    for (int k = k0; k < k0 + EE/8; k++)
        acc = fmaf(su[k], w[k*36 + j], acc);
    part[s][j] = acc;
    __syncthreads();
    if (threadIdx.x < 36) {
        float t = 0.0f;
        #pragma unroll
        for (int ss = 0; ss < 8; ss++) t += part[ss][threadIdx.x];
        dbc[row*36 + threadIdx.x] = t;
    }
}

// ---------------- dt = softplus(dbc[:, :4] @ dt_w + dt_b) ------------------
__global__ void dt_kernel(const float* __restrict__ dbc,
                          const float* __restrict__ dtw,
                          const float* __restrict__ dtb,
                          float* __restrict__ dt)
{
    int g = blockIdx.x * blockDim.x + threadIdx.x;   // TT*EE
    if (g >= TT*EE) return;
    int e = g % EE, row = g / EE;
    float v = dtb[e];
    #pragma unroll
    for (int r = 0; r < 4; r++)
        v = fmaf(dbc[row*36 + r], dtw[r*EE + e], v);
    dt[g] = softplus_f(v);
}

// ---------------- scan pass A: per-chunk (prod dA, h'|h0=0) ----------------
__global__ void scan_chunk_kernel(const float* __restrict__ dtp,
                                  const float* __restrict__ up,
                                  const float* __restrict__ dbc,
                                  const float* __restrict__ A_log,
                                  float* __restrict__ cP, float* __restrict__ cH)
{
    int g = blockIdx.x * blockDim.x + threadIdx.x;
    int e = g % EE;
    int n = (g / EE) % NNS;
    int c = (g / (EE*NNS)) % NCH;
    int b =  g / (EE*NNS*NCH);
    float Aen = -expf(A_log[e*NNS + n]);
    float p = 1.0f, h = 0.0f;
    int rbase = b*LL + c*TCH;
    for (int t = 0; t < TCH; t++) {
        int row   = rbase + t;
        float dtv = dtp[(size_t)row*EE + e];
        float uv  = up [(size_t)row*EE + e];
        float bv  = dbc[row*36 + 4 + n];
        float dA  = expf(dtv * Aen);
        p *= dA;
        h = fmaf(h, dA, dtv * uv * bv);
    }
    size_t idx = ((size_t)((b*NCH + c)*NNS + n))*EE + e;
    cP[idx] = p; cH[idx] = h;
}

// ---------------- scan pass B: sequential carry across 16 chunks -----------
__global__ void scan_carry_kernel(const float* __restrict__ cP,
                                  const float* __restrict__ cH,
                                  float* __restrict__ hinit)
{
    int g = blockIdx.x * blockDim.x + threadIdx.x;   // BB*NNS*EE
    if (g >= BB*NNS*EE) return;
    int e = g % EE;
    int n = (g / EE) % NNS;
    int b =  g / (EE*NNS);
    float h = 0.0f;
    for (int c = 0; c < NCH; c++) {
        size_t idx = ((size_t)((b*NCH + c)*NNS + n))*EE + e;
        hinit[idx] = h;
        h = fmaf(cP[idx], h, cH[idx]);
    }
}

// ---------------- scan pass C: rescan + gate; writes y as bf16 hi/lo -------
__global__ void scan_y_kernel(const float* __restrict__ dtp,
                              const float* __restrict__ up,
                              const float* __restrict__ dbc,
                              const float* __restrict__ hinit,
                              const float* __restrict__ A_log,
                              const float* __restrict__ Dv,
                              const float* __restrict__ proj,
                              __nv_bfloat16* __restrict__ yh,
                              __nv_bfloat16* __restrict__ yl)
{
    int g = blockIdx.x * blockDim.x + threadIdx.x;
    int n = g % NNS;
    int e = (g / NNS) % EE;
    int c = (g / (NNS*EE)) % NCH;
    int b =  g / (NNS*EE*NCH);
    float Aen  = -expf(A_log[e*NNS + n]);
    float h    = hinit[((size_t)((b*NCH + c)*NNS + n))*EE + e];
    float Dval = Dv[e];
    int t0 = c*TCH;
    for (int t = t0; t < t0 + TCH; t++) {
        int row   = b*LL + t;
        float dtv = dtp[(size_t)row*EE + e];
        float uv  = up [(size_t)row*EE + e];
        float bv  = dbc[row*36 + 4  + n];
        float cv  = dbc[row*36 + 20 + n];
        h = fmaf(h, expf(dtv * Aen), dtv * uv * bv);
        float part = h * cv;
        part += __shfl_xor_sync(0xffffffffu, part, 8);
        part += __shfl_xor_sync(0xffffffffu, part, 4);
        part += __shfl_xor_sync(0xffffffffu, part, 2);
        part += __shfl_xor_sync(0xffffffffu, part, 1);
        if (n == 0) {
            float gate = proj[(size_t)row*(2*EE) + EE + e];
            float yv = (part + uv*Dval) * sigmoid_f(gate);
            size_t yi = (size_t)row*EE + e;
            __nv_bfloat16 hb = __float2bfloat16(yv);
            yh[yi] = hb;
            yl[yi] = __float2bfloat16(yv - __bfloat162float(hb));
        }
    }
}

// ---------------- fractal accumulation: hs += (0.5/C)*sum_z t3[z] ----------
__global__ void frac_add3_kernel(float* __restrict__ hs, const float* __restrict__ t3, int n)
{
    int g = blockIdx.x * blockDim.x + threadIdx.x;
    if (g < n)
        hs[g] = fmaf(t3[g] + t3[n + g] + t3[2*n + g], 0.5f/3.0f, hs[g]);
}

// ---------------- host orchestration ----------------
extern "C" void kernel_launch(void* const* d_in, const int* in_sizes, int n_in,
                              void* d_out, int out_size)
{
    const int*   input_ids = (const int*)  d_in[0];
    const float* tok_emb   = (const float*)d_in[1];
    const float* pos_emb   = (const float*)d_in[2];
    const float* ln_w      = (const float*)d_in[3];
    const float* ln_b      = (const float*)d_in[4];
    const float* in_w      = (const float*)d_in[5];
    const float* in_b      = (const float*)d_in[6];
    const float* conv_w    = (const float*)d_in[7];
    const float* conv_b    = (const float*)d_in[8];
    const float* xproj_w   = (const float*)d_in[9];
    const float* dt_w      = (const float*)d_in[10];
    const float* dt_b      = (const float*)d_in[11];
    const float* A_log     = (const float*)d_in[12];
    const float* Dvec      = (const float*)d_in[13];
    const float* out_w     = (const float*)d_in[14];
    const float* out_b     = (const float*)d_in[15];
    const float* frac_w    = (const float*)d_in[16];
    const float* frac_b    = (const float*)d_in[17];
    const float* fln_w     = (const float*)d_in[18];
    const float* fln_b     = (const float*)d_in[19];
    float* outp = (float*)d_out;

    cudaFuncSetAttribute(mma_gemm, cudaFuncAttributeMaxDynamicSharedMemorySize,
                         MM_SMEM);

    float *hs, *proj, *u, *dbc, *dt, *cP, *cH, *hinit, *t3;
    cudaGetSymbolAddress((void**)&hs,    g_hs);
    cudaGetSymbolAddress((void**)&proj,  g_proj);
    cudaGetSymbolAddress((void**)&u,     g_u);
    cudaGetSymbolAddress((void**)&dbc,   g_dbc);
    cudaGetSymbolAddress((void**)&dt,    g_dt);
    cudaGetSymbolAddress((void**)&cP,    g_cP);
    cudaGetSymbolAddress((void**)&cH,    g_cH);
    cudaGetSymbolAddress((void**)&hinit, g_hinit);
    cudaGetSymbolAddress((void**)&t3,    g_t3);

    __nv_bfloat16 *Ah, *Al, *Ah2, *Al2, *F1h, *F1l, *F2h, *F2l;
    __nv_bfloat16 *Wih, *Wil, *Woh, *Wol, *Wfh, *Wfl;
    cudaGetSymbolAddress((void**)&Ah,  g_Ah);
    cudaGetSymbolAddress((void**)&Al,  g_Al);
    cudaGetSymbolAddress((void**)&Ah2, g_Ah2);
    cudaGetSymbolAddress((void**)&Al2, g_Al2);
    cudaGetSymbolAddress((void**)&F1h, g_F1h);
    cudaGetSymbolAddress((void**)&F1l, g_F1l);
    cudaGetSymbolAddress((void**)&F2h, g_F2h);
    cudaGetSymbolAddress((void**)&F2l, g_F2l);
    cudaGetSymbolAddress((void**)&Wih, g_Wih);
    cudaGetSymbolAddress((void**)&Wil, g_Wil);
    cudaGetSymbolAddress((void**)&Woh, g_Woh);
    cudaGetSymbolAddress((void**)&Wol, g_Wol);
    cudaGetSymbolAddress((void**)&Wfh, g_Wfh);
    cudaGetSymbolAddress((void**)&Wfl, g_Wfl);

    const int EW  = TT*HH;
    const int EWE = TT*EE;
    const int SCAN_T = BB*NCH*NNS*EE;
    const long ZF = (long)TT*HH;       // fractal per-branch stride

    // one-time weight split/transpose for ALL layers (batched over z)
    convW_kernel<<<dim3(2*EE/32, HH/32, NLAYER), 256>>>(in_w,  Wih, Wil, HH, 2*EE);
    convW_kernel<<<dim3(HH/32, EE/32, NLAYER), 256>>>(out_w, Woh, Wol, EE, HH);
    convW_kernel<<<dim3(HH/32, HH/32, NLAYER*CC), 256>>>(frac_w, Wfh, Wfl, HH, HH);

    embed_kernel<<<(EW + 255)/256, 256>>>(input_ids, tok_emb, pos_emb, hs);

    for (int l = 0; l < NLAYER; l++) {
        // x = LN(hs) -> bf16 hi/lo only (feeds GEMM directly)
        ln_kernel<<<TT, 256>>>(hs, ln_w + l*HH, ln_b + l*HH, nullptr, Ah, Al);
        // proj = x @ in_w + in_b  (4096 x 768 x 3072)
        mma_gemm<<<dim3(2*EE/64, TT/128), 256, MM_SMEM>>>(
            Ah, Al, Wih + (size_t)l*HH*2*EE, Wil + (size_t)l*HH*2*EE,
            in_b + l*2*EE, nullptr, proj, nullptr, nullptr,
            HH, 2*EE, 0, 0, 0, 0, 0, 0);
        // u = silu(causal_dwconv(proj[:, :E]))
        conv_silu_kernel<<<(EWE + 255)/256, 256>>>(proj, conv_w + l*EE*4, conv_b + l*EE, u);
        // dbc = u @ xproj_w
        dbc_kernel<<<TT, 288>>>(u, xproj_w + (size_t)l*EE*36, dbc);
        // dt = softplus(dbc[:, :4] @ dt_w + dt_b)
        dt_kernel<<<(EWE + 255)/256, 256>>>(dbc, dt_w + l*RRK*EE, dt_b + l*EE, dt);
        // chunked selective scan; pass C emits y as bf16 splits into Ah/Al
        scan_chunk_kernel<<<SCAN_T/256, 256>>>(dt, u, dbc, A_log + (size_t)l*EE*NNS, cP, cH);
        scan_carry_kernel<<<(BB*NNS*EE + 255)/256, 256>>>(cP, cH, hinit);
        scan_y_kernel<<<SCAN_T/256, 256>>>(dt, u, dbc, hinit,
            A_log + (size_t)l*EE*NNS, Dvec + l*EE, proj, Ah, Al);
        // hs = y @ out_w + out_b + hs; also emit hs splits for fractal input
        mma_gemm<<<dim3(HH/64, TT/128), 256, MM_SMEM>>>(
            Ah, Al, Woh + (size_t)l*EE*HH, Wol + (size_t)l*EE*HH,
            out_b + l*HH, hs, hs, Ah2, Al2,
            EE, HH, 0, 0, 0, 0, 0, 0);
        // fractal refinement: 3 independent branches batched over blockIdx.z
        const __nv_bfloat16* Wfh_l = Wfh + (size_t)l*CC*HH*HH;
        const __nv_bfloat16* Wfl_l = Wfl + (size_t)l*CC*HH*HH;
        const float* fb_l = frac_b + (size_t)l*CC*HH;
        // t1_z = silu(hs @ W_z + b_z)
        mma_gemm<<<dim3(HH/64, TT/128, CC), 256, MM_SMEM>>>(
            Ah2, Al2, Wfh_l, Wfl_l, fb_l, nullptr, nullptr, F1h, F1l,
            HH, HH, 1, 0, 0, (long)HH*HH, HH, ZF);
        // t2_z = silu(t1_z @ W_z + b_z)
        mma_gemm<<<dim3(HH/64, TT/128, CC), 256, MM_SMEM>>>(
            F1h, F1l, Wfh_l, Wfl_l, fb_l, nullptr, nullptr, F2h, F2l,
            HH, HH, 1, 0, ZF, (long)HH*HH, HH, ZF);
        // t3_z = silu(t2_z @ W_z + b_z)
        mma_gemm<<<dim3(HH/64, TT/128, CC), 256, MM_SMEM>>>(
            F2h, F2l, Wfh_l, Wfl_l, fb_l, nullptr, t3, nullptr, nullptr,
            HH, HH, 1, 0, ZF, (long)HH*HH, HH, ZF);
        // hs += (0.5/C) * sum_z t3_z
        frac_add3_kernel<<<(EW + 255)/256, 256>>>(hs, t3, EW);
    }

    // final layernorm -> output (float32)
    ln_kernel<<<TT, 256>>>(hs, fln_w, fln_b, outp, nullptr, nullptr);
    (void)in_sizes; (void)n_in; (void)out_size;
}

// round 16
// speedup vs baseline: 2.0196x; 1.1092x over previous
#include <cuda_runtime.h>
#include <cuda_bf16.h>
#include <math.h>
#include <stdint.h>

// ---------------- problem constants (fixed by the reference) ----------------
#define BB 2
#define LL 2048
#define HH 768
#define EE 1536
#define NNS 16           // state dim N
#define RRK 4            // dt rank R
#define CC 3
#define NLAYER 8
#define TT (BB*LL)       // 4096 rows
#define NCH 16           // scan chunks per sequence
#define TCH (LL/NCH)     // 128 steps per chunk

// ---------------- scratch (device globals: no runtime allocation) ----------
__device__ float g_hs  [TT*HH];
__device__ float g_proj[TT*2*EE];
__device__ float g_u   [TT*EE];
__device__ float g_dbc [TT*36];
__device__ float g_dt  [TT*EE];
__device__ float g_cP   [BB*NCH*NNS*EE];
__device__ float g_cH   [BB*NCH*NNS*EE];
__device__ float g_hinit[BB*NCH*NNS*EE];
__device__ float g_t3  [CC*TT*HH];       // fractal 3rd-step outputs per branch

// bf16 hi/lo split buffers (activations)
__device__ __nv_bfloat16 g_Ah [TT*EE];   // layer activations (max K = 1536)
__device__ __nv_bfloat16 g_Al [TT*EE];
__device__ __nv_bfloat16 g_Ah2[TT*HH];   // hs splits (fractal input, z-shared)
__device__ __nv_bfloat16 g_Al2[TT*HH];
__device__ __nv_bfloat16 g_F1h[CC*TT*HH], g_F1l[CC*TT*HH];  // fractal t1 per branch
__device__ __nv_bfloat16 g_F2h[CC*TT*HH], g_F2l[CC*TT*HH];  // fractal t2 per branch

// precomputed weight splits, transposed to [N,K] per layer (all layers upfront)
__device__ __nv_bfloat16 g_Wih[(size_t)NLAYER*HH*2*EE];
__device__ __nv_bfloat16 g_Wil[(size_t)NLAYER*HH*2*EE];
__device__ __nv_bfloat16 g_Woh[(size_t)NLAYER*EE*HH];
__device__ __nv_bfloat16 g_Wol[(size_t)NLAYER*EE*HH];
__device__ __nv_bfloat16 g_Wfh[(size_t)NLAYER*CC*HH*HH];
__device__ __nv_bfloat16 g_Wfl[(size_t)NLAYER*CC*HH*HH];

// ---------------- helpers ----------------
__device__ __forceinline__ float silu_f(float v)    { return v / (1.0f + expf(-v)); }
__device__ __forceinline__ float sigmoid_f(float v) { return 1.0f / (1.0f + expf(-v)); }
__device__ __forceinline__ float softplus_f(float v){ return (v > 20.0f) ? v : log1pf(expf(v)); }

__device__ __forceinline__ void mma16816(float* d, const uint32_t* a, const uint32_t* b)
{
    asm volatile(
        "mma.sync.aligned.m16n8k16.row.col.f32.bf16.bf16.f32 "
        "{%0,%1,%2,%3}, {%4,%5,%6,%7}, {%8,%9}, {%0,%1,%2,%3};"
        : "+f"(d[0]), "+f"(d[1]), "+f"(d[2]), "+f"(d[3])
        : "r"(a[0]), "r"(a[1]), "r"(a[2]), "r"(a[3]), "r"(b[0]), "r"(b[1]));
}
__device__ __forceinline__ void ldsm4(uint32_t* r, const __nv_bfloat16* p)
{
    uint32_t sa = (uint32_t)__cvta_generic_to_shared(p);
    asm volatile("ldmatrix.sync.aligned.m8n8.x4.shared.b16 {%0,%1,%2,%3}, [%4];"
                 : "=r"(r[0]), "=r"(r[1]), "=r"(r[2]), "=r"(r[3]) : "r"(sa));
}
__device__ __forceinline__ void cpa16(__nv_bfloat16* s, const __nv_bfloat16* g)
{
    uint32_t sa = (uint32_t)__cvta_generic_to_shared(s);
    asm volatile("cp.async.cg.shared.global [%0], [%1], 16;" :: "r"(sa), "l"(g));
}
__device__ __forceinline__ void split_store(__nv_bfloat16* Oh, __nv_bfloat16* Ol,
                                            size_t idx, float v0, float v1)
{
    __nv_bfloat16 h0 = __float2bfloat16(v0), h1 = __float2bfloat16(v1);
    __nv_bfloat162 hv; hv.x = h0; hv.y = h1;
    *(__nv_bfloat162*)(Oh + idx) = hv;
    __nv_bfloat162 lv;
    lv.x = __float2bfloat16(v0 - __bfloat162float(h0));
    lv.y = __float2bfloat16(v1 - __bfloat162float(h1));
    *(__nv_bfloat162*)(Ol + idx) = lv;
}

// ---------------- embedding ----------------
__global__ void embed_kernel(const int* __restrict__ ids,
                             const float* __restrict__ tok,
                             const float* __restrict__ pos,
                             float* __restrict__ hs)
{
    int g = blockIdx.x * blockDim.x + threadIdx.x;   // TT*HH
    if (g >= TT*HH) return;
    int h   = g % HH;
    int row = g / HH;
    int t   = row % LL;
    hs[g] = tok[(size_t)ids[row]*HH + h] + pos[(size_t)t*HH + h];
}

// ---------------- layernorm; optional float out and/or bf16 hi/lo split ----
__global__ __launch_bounds__(256) void ln_kernel(const float* __restrict__ in,
                                                 const float* __restrict__ w,
                                                 const float* __restrict__ b,
                                                 float* __restrict__ out,
                                                 __nv_bfloat16* __restrict__ oh,
                                                 __nv_bfloat16* __restrict__ ol)
{
    __shared__ float red[256];
    int row = blockIdx.x, tid = threadIdx.x;
    const float* x = in + (size_t)row*HH;
    float v0 = x[tid], v1 = x[tid+256], v2 = x[tid+512];
    red[tid] = v0 + v1 + v2;
    __syncthreads();
    #pragma unroll
    for (int s = 128; s > 0; s >>= 1) { if (tid < s) red[tid] += red[tid+s]; __syncthreads(); }
    float mean = red[0] * (1.0f/768.0f);
    __syncthreads();
    float d0 = v0-mean, d1 = v1-mean, d2 = v2-mean;
    red[tid] = d0*d0 + d1*d1 + d2*d2;
    __syncthreads();
    #pragma unroll
    for (int s = 128; s > 0; s >>= 1) { if (tid < s) red[tid] += red[tid+s]; __syncthreads(); }
    float inv = rsqrtf(red[0] * (1.0f/768.0f) + 1e-5f);
    size_t base = (size_t)row*HH;
    #pragma unroll
    for (int q = 0; q < 3; q++) {
        float dd = (q == 0) ? d0 : (q == 1) ? d1 : d2;
        int h = tid + q*256;
        float vv = dd*inv*w[h] + b[h];
        if (out) out[base + h] = vv;
        if (oh) {
            __nv_bfloat16 hb = __float2bfloat16(vv);
            oh[base + h] = hb;
            ol[base + h] = __float2bfloat16(vv - __bfloat162float(hb));
        }
    }
}

// ---------------- weight transpose + split: W[K,N] -> Wt[N,K] hi/lo --------
__global__ __launch_bounds__(256) void convW_kernel(const float* __restrict__ W,
                                                    __nv_bfloat16* __restrict__ Wth,
                                                    __nv_bfloat16* __restrict__ Wtl,
                                                    int Kd, int Nd)
{
    __shared__ float tile[32][33];
    size_t zo = (size_t)blockIdx.z * Kd * Nd;
    W += zo; Wth += zo; Wtl += zo;
    int kb = blockIdx.y*32, nb = blockIdx.x*32;
    int tx = threadIdx.x & 31, ty = threadIdx.x >> 5;   // 32x8
    #pragma unroll
    for (int r = 0; r < 32; r += 8)
        tile[ty+r][tx] = W[(size_t)(kb+ty+r)*Nd + nb+tx];
    __syncthreads();
    #pragma unroll
    for (int r = 0; r < 32; r += 8) {
        int n = nb + ty + r, k = kb + tx;
        float v = tile[tx][ty+r];
        __nv_bfloat16 h = __float2bfloat16(v);
        Wth[(size_t)n*Kd + k] = h;
        Wtl[(size_t)n*Kd + k] = __float2bfloat16(v - __bfloat162float(h));
    }
}

// ---------------- tensor-core split-bf16 GEMM: 3-stage cp.async ------------
// C = act(A*W + bias) [+res] [accum] ; optional bf16 hi/lo split output.
// D = Ah*Bh^T + Ah*Bl^T + Al*Bh^T, fp32 accumulate; product-major MMA order
// so same-accumulator HMMAs are spaced 8 apart (breaks RAW chains).
// Block 128(M)x64(N), 8 warps (4m x 2n), warp tile 32x32, KC=32, 3 stages.
// blockIdx.z batches independent GEMMs via az/wz/bz/oz element strides.
#define KC  32
#define AST 40                          // smem row stride (bf16): conflict-free
#define TILE_A (128*AST)
#define TILE_B (64*AST)
#define STAGE_E (2*TILE_A + 2*TILE_B)   // 15360 elems
#define MM_SMEM (3*STAGE_E*2)           // 92160 bytes

__global__ __launch_bounds__(256, 2) void mma_gemm(
    const __nv_bfloat16* __restrict__ Ah, const __nv_bfloat16* __restrict__ Al,
    const __nv_bfloat16* __restrict__ Bh, const __nv_bfloat16* __restrict__ Bl,
    const float* __restrict__ bias, const float* __restrict__ Rres,
    float* __restrict__ Cout,
    __nv_bfloat16* __restrict__ Oh, __nv_bfloat16* __restrict__ Ol,
    int Kd, int Nd, int act, int accum,
    long az, long wz, int bz, long oz)
{
    extern __shared__ __align__(16) __nv_bfloat16 sm[];
    const int tid = threadIdx.x, wid = tid >> 5, lane = tid & 31;
    const int bm = blockIdx.y*128, bn = blockIdx.x*64;
    const int wm = (wid & 3)*32, wn = (wid >> 2)*32;
    const int r = lane >> 2, c = lane & 3;
    const int z = blockIdx.z;

    Ah += (size_t)az*z; Al += (size_t)az*z;
    Bh += (size_t)wz*z; Bl += (size_t)wz*z;
    bias += (size_t)bz*z;

    float acc[2][4][4];
    #pragma unroll
    for (int mt = 0; mt < 2; mt++)
        #pragma unroll
        for (int nt = 0; nt < 4; nt++)
            #pragma unroll
            for (int j = 0; j < 4; j++) acc[mt][nt][j] = 0.0f;

    auto issue_fill = [&](int stage, int kc) {
        const size_t koff = (size_t)kc * KC;
        __nv_bfloat16* S = sm + stage*STAGE_E;
        #pragma unroll
        for (int i = 0; i < 2; i++) {
            int q = tid + i*256;              // 0..511 -> A rows
            int row = q >> 2, col = (q & 3)*8;
            int so = row*AST + col;
            size_t ga = (size_t)(bm + row)*Kd + koff + col;
            cpa16(S + so,          Ah + ga);
            cpa16(S + TILE_A + so, Al + ga);
        }
        {
            int row = tid >> 2, col = (tid & 3)*8;   // B rows 0..63
            int so = row*AST + col;
            size_t gb = (size_t)(bn + row)*Kd + koff + col;
            cpa16(S + 2*TILE_A + so,          Bh + gb);
            cpa16(S + 2*TILE_A + TILE_B + so, Bl + gb);
        }
        asm volatile("cp.async.commit_group;" ::: "memory");
    };

    const int nkc = Kd / KC;
    issue_fill(0, 0);
    issue_fill(1, 1);
    int stage = 0;
    for (int kc = 0; kc < nkc; kc++) {
        if (kc + 1 < nkc) { asm volatile("cp.async.wait_group 1;" ::: "memory"); }
        else              { asm volatile("cp.async.wait_group 0;" ::: "memory"); }
        __syncthreads();
        if (kc + 2 < nkc) {
            int ns = stage + 2; if (ns >= 3) ns -= 3;
            issue_fill(ns, kc + 2);
        }
        const __nv_bfloat16* S   = sm + stage*STAGE_E;
        const __nv_bfloat16* Ash = S;
        const __nv_bfloat16* Asl = S + TILE_A;
        const __nv_bfloat16* Bsh = S + 2*TILE_A;
        const __nv_bfloat16* Bsl = S + 2*TILE_A + TILE_B;

        #pragma unroll
        for (int kk = 0; kk < KC; kk += 16) {
            uint32_t afh[2][4], afl[2][4], bh[2][4], bl[2][4];
            #pragma unroll
            for (int mt = 0; mt < 2; mt++) {
                int ae = (wm + mt*16 + (lane & 15))*AST + kk + ((lane >> 4)*8);
                ldsm4(afh[mt], Ash + ae);
                ldsm4(afl[mt], Asl + ae);
            }
            #pragma unroll
            for (int nt2 = 0; nt2 < 2; nt2++) {
                int be = (wn + nt2*16 + ((lane >> 4)*8) + (lane & 7))*AST
                         + kk + (((lane >> 3) & 1)*8);
                ldsm4(bh[nt2], Bsh + be);
                ldsm4(bl[nt2], Bsl + be);
            }
            // product-major: 8 independent accumulators between reuses
            #pragma unroll
            for (int mt = 0; mt < 2; mt++)
                #pragma unroll
                for (int nt2 = 0; nt2 < 2; nt2++)
                    #pragma unroll
                    for (int h = 0; h < 2; h++)
                        mma16816(acc[mt][nt2*2 + h], afh[mt], bh[nt2] + 2*h);
            #pragma unroll
            for (int mt = 0; mt < 2; mt++)
                #pragma unroll
                for (int nt2 = 0; nt2 < 2; nt2++)
                    #pragma unroll
                    for (int h = 0; h < 2; h++)
                        mma16816(acc[mt][nt2*2 + h], afh[mt], bl[nt2] + 2*h);
            #pragma unroll
            for (int mt = 0; mt < 2; mt++)
                #pragma unroll
                for (int nt2 = 0; nt2 < 2; nt2++)
                    #pragma unroll
                    for (int h = 0; h < 2; h++)
                        mma16816(acc[mt][nt2*2 + h], afl[mt], bh[nt2] + 2*h);
        }
        stage++; if (stage >= 3) stage = 0;
    }

    // epilogue: fragment (rows r, r+8; cols 2c, 2c+1)
    #pragma unroll
    for (int nt = 0; nt < 4; nt++) {
        int n = bn + wn + nt*8 + 2*c;
        float2 bv = *(const float2*)(bias + n);
        #pragma unroll
        for (int mt = 0; mt < 2; mt++) {
            #pragma unroll
            for (int half = 0; half < 2; half++) {
                int m = bm + wm + mt*16 + r + half*8;
                float v0 = acc[mt][nt][half*2+0] + bv.x;
                float v1 = acc[mt][nt][half*2+1] + bv.y;
                if (act) { v0 = silu_f(v0); v1 = silu_f(v1); }
                size_t idx = (size_t)m * Nd + n + (size_t)oz*z;
                if (Rres) { float2 rv = *(const float2*)(Rres + idx); v0 += rv.x; v1 += rv.y; }
                if (Cout) {
                    if (accum) {
                        float2 ov = *(const float2*)(Cout + idx);
                        v0 += ov.x; v1 += ov.y;
                    }
                    float2 w2; w2.x = v0; w2.y = v1;
                    *(float2*)(Cout + idx) = w2;
                }
                if (Oh) split_store(Oh, Ol, idx, v0, v1);
            }
        }
    }
}

// ---------------- causal depthwise conv (K=4) + SiLU, reads xm from proj ----
__global__ void conv_silu_kernel(const float* __restrict__ proj,
                                 const float* __restrict__ cw,
                                 const float* __restrict__ cb,
                                 float* __restrict__ u)
{
    int g = blockIdx.x * blockDim.x + threadIdx.x;   // TT*EE
    if (g >= TT*EE) return;
    int e   = g % EE;
    int row = g / EE;
    int t   = row % LL;
    int b   = row / LL;
    float acc = cb[e];
    #pragma unroll
    for (int j = 0; j < 4; j++) {
        int tt = t - 3 + j;
        if (tt >= 0)
            acc = fmaf(proj[(size_t)(b*LL + tt)*(2*EE) + e], cw[e*4 + j], acc);
    }
    u[g] = silu_f(acc);
}

// ---------------- dbc = u @ xproj_w  (4096 x 1536 x 36 skinny GEMM) --------
__global__ __launch_bounds__(288) void dbc_kernel(const float* __restrict__ u,
                                                  const float* __restrict__ w,
                                                  float* __restrict__ dbc)
{
    __shared__ float su[EE];
    __shared__ float part[8][36];
    int row = blockIdx.x;
    for (int i = threadIdx.x; i < EE; i += 288) su[i] = u[(size_t)row*EE + i];
    __syncthreads();
    int j = threadIdx.x % 36, s = threadIdx.x / 36;   // 36 cols x 8 k-slices
    float acc = 0.0f;
    int k0 = s * (EE/8);
    for (int k = k0; k < k0 + EE/8; k++)
        acc = fmaf(su[k], w[k*36 + j], acc);
    part[s][j] = acc;
    __syncthreads();
    if (threadIdx.x < 36) {
        float t = 0.0f;
        #pragma unroll
        for (int ss = 0; ss < 8; ss++) t += part[ss][threadIdx.x];
        dbc[row*36 + threadIdx.x] = t;
    }
}

// ---------------- dt = softplus(dbc[:, :4] @ dt_w + dt_b) ------------------
__global__ void dt_kernel(const float* __restrict__ dbc,
                          const float* __restrict__ dtw,
                          const float* __restrict__ dtb,
                          float* __restrict__ dt)
{
    int g = blockIdx.x * blockDim.x + threadIdx.x;   // TT*EE
    if (g >= TT*EE) return;
    int e = g % EE, row = g / EE;
    float v = dtb[e];
    #pragma unroll
    for (int r = 0; r < 4; r++)
        v = fmaf(dbc[row*36 + r], dtw[r*EE + e], v);
    dt[g] = softplus_f(v);
}

// ---------------- scan pass A (n-folded): per-chunk (prod dA, h'|h0=0) -----
// one thread per (e, chunk, batch); all 16 n-states in registers.
// dt/u read ONCE per step (16x less traffic); dbc reads are warp-uniform.
__global__ __launch_bounds__(256) void scan_chunk_kernel(
    const float* __restrict__ dtp, const float* __restrict__ up,
    const float* __restrict__ dbc, const float* __restrict__ A_log,
    float* __restrict__ cP, float* __restrict__ cH)
{
    int g = blockIdx.x * blockDim.x + threadIdx.x;   // BB*NCH*EE
    if (g >= BB*NCH*EE) return;
    int e = g % EE;
    int c = (g / EE) % NCH;
    int b =  g / (EE*NCH);
    float Aen[NNS], p[NNS], h[NNS];
    #pragma unroll
    for (int n = 0; n < NNS; n++) {
        Aen[n] = -expf(A_log[e*NNS + n]);
        p[n] = 1.0f; h[n] = 0.0f;
    }
    int rbase = b*LL + c*TCH;
    for (int t = 0; t < TCH; t++) {
        int row   = rbase + t;
        float dtv = dtp[(size_t)row*EE + e];
        float uv  = up [(size_t)row*EE + e];
        float du  = dtv * uv;
        const float* bvp = dbc + row*36 + 4;
        #pragma unroll
        for (int n = 0; n < NNS; n++) {
            float dA = expf(dtv * Aen[n]);
            p[n] *= dA;
            h[n] = fmaf(h[n], dA, du * bvp[n]);
        }
    }
    size_t base = ((size_t)((b*NCH + c)*NNS))*EE + e;
    #pragma unroll
    for (int n = 0; n < NNS; n++) {
        cP[base + (size_t)n*EE] = p[n];
        cH[base + (size_t)n*EE] = h[n];
    }
}

// ---------------- scan pass B: sequential carry across 16 chunks -----------
__global__ void scan_carry_kernel(const float* __restrict__ cP,
                                  const float* __restrict__ cH,
                                  float* __restrict__ hinit)
{
    int g = blockIdx.x * blockDim.x + threadIdx.x;   // BB*NNS*EE
    if (g >= BB*NNS*EE) return;
    int e = g % EE;
    int n = (g / EE) % NNS;
    int b =  g / (EE*NNS);
    float h = 0.0f;
    for (int c = 0; c < NCH; c++) {
        size_t idx = ((size_t)((b*NCH + c)*NNS + n))*EE + e;
        hinit[idx] = h;
        h = fmaf(cP[idx], h, cH[idx]);
    }
}

// ---------------- scan pass C (n-folded): rescan + gate -> y bf16 hi/lo ----
__global__ __launch_bounds__(256) void scan_y_kernel(
    const float* __restrict__ dtp, const float* __restrict__ up,
    const float* __restrict__ dbc, const float* __restrict__ hinit,
    const float* __restrict__ A_log, const float* __restrict__ Dv,
    const float* __restrict__ proj,
    __nv_bfloat16* __restrict__ yh, __nv_bfloat16* __restrict__ yl)
{
    int g = blockIdx.x * blockDim.x + threadIdx.x;   // BB*NCH*EE
    if (g >= BB*NCH*EE) return;
    int e = g % EE;
    int c = (g / EE) % NCH;
    int b =  g / (EE*NCH);
    float Aen[NNS], h[NNS];
    size_t hbase = ((size_t)((b*NCH + c)*NNS))*EE + e;
    #pragma unroll
    for (int n = 0; n < NNS; n++) {
        Aen[n] = -expf(A_log[e*NNS + n]);
        h[n] = hinit[hbase + (size_t)n*EE];
    }
    float Dval = Dv[e];
    int rbase = b*LL + c*TCH;
    for (int t = 0; t < TCH; t++) {
        int row   = rbase + t;
        float dtv = dtp[(size_t)row*EE + e];
        float uv  = up [(size_t)row*EE + e];
        float du  = dtv * uv;
        const float* bvp = dbc + row*36 + 4;
        const float* cvp = dbc + row*36 + 20;
        float acc = 0.0f;
        #pragma unroll
        for (int n = 0; n < NNS; n++) {
            h[n] = fmaf(h[n], expf(dtv * Aen[n]), du * bvp[n]);
            acc = fmaf(h[n], cvp[n], acc);
        }
        float gate = proj[(size_t)row*(2*EE) + EE + e];
        float yv = (acc + uv*Dval) * sigmoid_f(gate);
        size_t yi = (size_t)row*EE + e;
        __nv_bfloat16 hb = __float2bfloat16(yv);
        yh[yi] = hb;
        yl[yi] = __float2bfloat16(yv - __bfloat162float(hb));
    }
}

// ---------------- fractal accumulation: hs += (0.5/C)*sum_z t3[z] ----------
__global__ void frac_add3_kernel(float* __restrict__ hs, const float* __restrict__ t3, int n)
{
    int g = blockIdx.x * blockDim.x + threadIdx.x;
    if (g < n)
        hs[g] = fmaf(t3[g] + t3[n + g] + t3[2*n + g], 0.5f/3.0f, hs[g]);
}

// ---------------- host orchestration ----------------
extern "C" void kernel_launch(void* const* d_in, const int* in_sizes, int n_in,
                              void* d_out, int out_size)
{
    const int*   input_ids = (const int*)  d_in[0];
    const float* tok_emb   = (const float*)d_in[1];
    const float* pos_emb   = (const float*)d_in[2];
    const float* ln_w      = (const float*)d_in[3];
    const float* ln_b      = (const float*)d_in[4];
    const float* in_w      = (const float*)d_in[5];
    const float* in_b      = (const float*)d_in[6];
    const float* conv_w    = (const float*)d_in[7];
    const float* conv_b    = (const float*)d_in[8];
    const float* xproj_w   = (const float*)d_in[9];
    const float* dt_w      = (const float*)d_in[10];
    const float* dt_b      = (const float*)d_in[11];
    const float* A_log     = (const float*)d_in[12];
    const float* Dvec      = (const float*)d_in[13];
    const float* out_w     = (const float*)d_in[14];
    const float* out_b     = (const float*)d_in[15];
    const float* frac_w    = (const float*)d_in[16];
    const float* frac_b    = (const float*)d_in[17];
    const float* fln_w     = (const float*)d_in[18];
    const float* fln_b     = (const float*)d_in[19];
    float* outp = (float*)d_out;

    cudaFuncSetAttribute(mma_gemm, cudaFuncAttributeMaxDynamicSharedMemorySize,
                         MM_SMEM);

    float *hs, *proj, *u, *dbc, *dt, *cP, *cH, *hinit, *t3;
    cudaGetSymbolAddress((void**)&hs,    g_hs);
    cudaGetSymbolAddress((void**)&proj,  g_proj);
    cudaGetSymbolAddress((void**)&u,     g_u);
    cudaGetSymbolAddress((void**)&dbc,   g_dbc);
    cudaGetSymbolAddress((void**)&dt,    g_dt);
    cudaGetSymbolAddress((void**)&cP,    g_cP);
    cudaGetSymbolAddress((void**)&cH,    g_cH);
    cudaGetSymbolAddress((void**)&hinit, g_hinit);
    cudaGetSymbolAddress((void**)&t3,    g_t3);

    __nv_bfloat16 *Ah, *Al, *Ah2, *Al2, *F1h, *F1l, *F2h, *F2l;
    __nv_bfloat16 *Wih, *Wil, *Woh, *Wol, *Wfh, *Wfl;
    cudaGetSymbolAddress((void**)&Ah,  g_Ah);
    cudaGetSymbolAddress((void**)&Al,  g_Al);
    cudaGetSymbolAddress((void**)&Ah2, g_Ah2);
    cudaGetSymbolAddress((void**)&Al2, g_Al2);
    cudaGetSymbolAddress((void**)&F1h, g_F1h);
    cudaGetSymbolAddress((void**)&F1l, g_F1l);
    cudaGetSymbolAddress((void**)&F2h, g_F2h);
    cudaGetSymbolAddress((void**)&F2l, g_F2l);
    cudaGetSymbolAddress((void**)&Wih, g_Wih);
    cudaGetSymbolAddress((void**)&Wil, g_Wil);
    cudaGetSymbolAddress((void**)&Woh, g_Woh);
    cudaGetSymbolAddress((void**)&Wol, g_Wol);
    cudaGetSymbolAddress((void**)&Wfh, g_Wfh);
    cudaGetSymbolAddress((void**)&Wfl, g_Wfl);

    const int EW  = TT*HH;
    const int EWE = TT*EE;
    const int SCAN_NF = BB*NCH*EE;     // n-folded scan thread count
    const long ZF = (long)TT*HH;       // fractal per-branch stride

    // one-time weight split/transpose for ALL layers (batched over z)
    convW_kernel<<<dim3(2*EE/32, HH/32, NLAYER), 256>>>(in_w,  Wih, Wil, HH, 2*EE);
    convW_kernel<<<dim3(HH/32, EE/32, NLAYER), 256>>>(out_w, Woh, Wol, EE, HH);
    convW_kernel<<<dim3(HH/32, HH/32, NLAYER*CC), 256>>>(frac_w, Wfh, Wfl, HH, HH);

    embed_kernel<<<(EW + 255)/256, 256>>>(input_ids, tok_emb, pos_emb, hs);

    for (int l = 0; l < NLAYER; l++) {
        // x = LN(hs) -> bf16 hi/lo only (feeds GEMM directly)
        ln_kernel<<<TT, 256>>>(hs, ln_w + l*HH, ln_b + l*HH, nullptr, Ah, Al);
        // proj = x @ in_w + in_b  (4096 x 768 x 3072)
        mma_gemm<<<dim3(2*EE/64, TT/128), 256, MM_SMEM>>>(
            Ah, Al, Wih + (size_t)l*HH*2*EE, Wil + (size_t)l*HH*2*EE,
            in_b + l*2*EE, nullptr, proj, nullptr, nullptr,
            HH, 2*EE, 0, 0, 0, 0, 0, 0);
        // u = silu(causal_dwconv(proj[:, :E]))
        conv_silu_kernel<<<(EWE + 255)/256, 256>>>(proj, conv_w + l*EE*4, conv_b + l*EE, u);
        // dbc = u @ xproj_w
        dbc_kernel<<<TT, 288>>>(u, xproj_w + (size_t)l*EE*36, dbc);
        // dt = softplus(dbc[:, :4] @ dt_w + dt_b)
        dt_kernel<<<(EWE + 255)/256, 256>>>(dbc, dt_w + l*RRK*EE, dt_b + l*EE, dt);
        // chunked selective scan (n-folded passes A and C)
        scan_chunk_kernel<<<(SCAN_NF + 255)/256, 256>>>(
            dt, u, dbc, A_log + (size_t)l*EE*NNS, cP, cH);
        scan_carry_kernel<<<(BB*NNS*EE + 255)/256, 256>>>(cP, cH, hinit);
        scan_y_kernel<<<(SCAN_NF + 255)/256, 256>>>(dt, u, dbc, hinit,
            A_log + (size_t)l*EE*NNS, Dvec + l*EE, proj, Ah, Al);
        // hs = y @ out_w + out_b + hs; also emit hs splits for fractal input
        mma_gemm<<<dim3(HH/64, TT/128), 256, MM_SMEM>>>(
            Ah, Al, Woh + (size_t)l*EE*HH, Wol + (size_t)l*EE*HH,
            out_b + l*HH, hs, hs, Ah2, Al2,
            EE, HH, 0, 0, 0, 0, 0, 0);
        // fractal refinement: 3 independent branches batched over blockIdx.z
        const __nv_bfloat16* Wfh_l = Wfh + (size_t)l*CC*HH*HH;
        const __nv_bfloat16* Wfl_l = Wfl + (size_t)l*CC*HH*HH;
        const float* fb_l = frac_b + (size_t)l*CC*HH;
        mma_gemm<<<dim3(HH/64, TT/128, CC), 256, MM_SMEM>>>(
            Ah2, Al2, Wfh_l, Wfl_l, fb_l, nullptr, nullptr, F1h, F1l,
            HH, HH, 1, 0, 0, (long)HH*HH, HH, ZF);
        mma_gemm<<<dim3(HH/64, TT/128, CC), 256, MM_SMEM>>>(
            F1h, F1l, Wfh_l, Wfl_l, fb_l, nullptr, nullptr, F2h, F2l,
            HH, HH, 1, 0, ZF, (long)HH*HH, HH, ZF);
        mma_gemm<<<dim3(HH/64, TT/128, CC), 256, MM_SMEM>>>(
            F2h, F2l, Wfh_l, Wfl_l, fb_l, nullptr, t3, nullptr, nullptr,
            HH, HH, 1, 0, ZF, (long)HH*HH, HH, ZF);
        // hs += (0.5/C) * sum_z t3_z
        frac_add3_kernel<<<(EW + 255)/256, 256>>>(hs, t3, EW);
    }

    // final layernorm -> output (float32)
    ln_kernel<<<TT, 256>>>(hs, fln_w, fln_b, outp, nullptr, nullptr);
    (void)in_sizes; (void)n_in; (void)out_size;
}